// round 6
// baseline (speedup 1.0000x reference)
#include <cuda_runtime.h>
#include <cuda_bf16.h>
#include <cstdint>

#define MAX_NODES 100032
#define MAX_EDGES 1600000
#define DIM 256
#define SCAN_B 1024
#define MAX_SCAN_BLOCKS 128

// Scratch (static device globals — no allocation allowed)
static __device__ float g_Y[(size_t)MAX_NODES * DIM];   // Y = X @ W
static __device__ int   g_cnt[MAX_NODES];
static __device__ int   g_off[MAX_NODES + 1];
static __device__ int   g_cur[MAX_NODES];
static __device__ int   g_part[MAX_SCAN_BLOCKS];
static __device__ int2  g_cv[MAX_EDGES];
// Pre-baked mma B fragments of W (bf16 hi/lo split), layout
// [h(2)][k16(16)][hl(2)][n8(16)][lane(32)] of uint2 {b0,b1} = 512 KB
static __device__ uint2 g_Wfrag[2 * 16 * 2 * 16 * 32];

// ---------------------------------------------------------------------------
// helpers
// ---------------------------------------------------------------------------
__device__ __forceinline__ uint32_t smem_u32(const void* p) {
    uint32_t a;
    asm("{ .reg .u64 t; cvta.to.shared.u64 t, %1; cvt.u32.u64 %0, t; }"
        : "=r"(a) : "l"(p));
    return a;
}
__device__ __forceinline__ void ldmatrix_x4(uint32_t* r, uint32_t addr) {
    asm volatile("ldmatrix.sync.aligned.m8n8.x4.shared.b16 {%0,%1,%2,%3}, [%4];"
                 : "=r"(r[0]), "=r"(r[1]), "=r"(r[2]), "=r"(r[3]) : "r"(addr));
}
__device__ __forceinline__ void mma_bf16(float* d, const uint32_t* a, uint2 b) {
    asm volatile(
        "mma.sync.aligned.m16n8k16.row.col.f32.bf16.bf16.f32 "
        "{%0,%1,%2,%3}, {%4,%5,%6,%7}, {%8,%9}, {%0,%1,%2,%3};"
        : "+f"(d[0]), "+f"(d[1]), "+f"(d[2]), "+f"(d[3])
        : "r"(a[0]), "r"(a[1]), "r"(a[2]), "r"(a[3]), "r"(b.x), "r"(b.y));
}
__device__ __forceinline__ uint32_t pack_bf16(float a, float b) {
    __nv_bfloat16 ha = __float2bfloat16(a);
    __nv_bfloat16 hb = __float2bfloat16(b);
    return ((uint32_t)__bfloat16_as_ushort(hb) << 16) |
            (uint32_t)__bfloat16_as_ushort(ha);
}

// ---------------------------------------------------------------------------
// W prep: bf16 split + per-lane mma B-fragment bake.
// ---------------------------------------------------------------------------
__global__ void wprep_kernel(const float* __restrict__ W) {
    int i = blockIdx.x * blockDim.x + threadIdx.x;
    if (i >= 32768) return;
    int lane = i & 31;
    int n8   = (i >> 5) & 15;
    int hl   = (i >> 9) & 1;
    int k16  = (i >> 10) & 15;
    int h    = (i >> 14) & 1;
    int n  = h * 128 + n8 * 8 + (lane >> 2);
    int kb = k16 * 16 + (lane & 3) * 2;
    uint32_t r[2];
    #pragma unroll
    for (int reg = 0; reg < 2; reg++) {
        int k0 = kb + reg * 8;
        float f0 = W[(size_t)k0 * 256 + n];
        float f1 = W[(size_t)(k0 + 1) * 256 + n];
        if (hl == 0) {
            r[reg] = pack_bf16(f0, f1);
        } else {
            float h0 = __bfloat162float(__float2bfloat16(f0));
            float h1 = __bfloat162float(__float2bfloat16(f1));
            r[reg] = pack_bf16(f0 - h0, f1 - h1);
        }
    }
    g_Wfrag[i] = make_uint2(r[0], r[1]);
}

// ---------------------------------------------------------------------------
// HMMA GEMM: g_Y = X @ W via bf16 3-product split (XhWh + XlWh + XhWl).
// ---------------------------------------------------------------------------
#define OFF_AL 67584
#define OFF_B0 135168
#define OFF_B1 167936
#define GEMM_SMEM 200704

__global__ __launch_bounds__(256, 1)
void gemm_tc_kernel(const float* __restrict__ X, int M) {
    extern __shared__ char smem[];
    const int tid   = threadIdx.x;
    const int lane  = tid & 31;
    const int wid   = tid >> 5;
    const int warpM = wid & 3;
    const int warpN = wid >> 2;
    const int rowBase = blockIdx.x * 128;
    const uint32_t sb = smem_u32(smem);

    // ---- load + convert X tile to bf16 hi/lo in smem (row stride 528B) ----
    {
        int r  = tid >> 1;
        int ch = (tid & 1) * 128;
        int grow = rowBase + r;
        const float4* xp = reinterpret_cast<const float4*>(
            X + (size_t)grow * 256 + ch);
        char* dH = smem + (size_t)r * 528 + ch * 2;
        char* dL = dH + OFF_AL;
        #pragma unroll 8
        for (int q = 0; q < 32; q++) {
            float4 v = make_float4(0.f, 0.f, 0.f, 0.f);
            if (grow < M) v = xp[q];
            uint32_t hi0 = pack_bf16(v.x, v.y);
            uint32_t hi1 = pack_bf16(v.z, v.w);
            float rx = v.x - __bfloat162float(__float2bfloat16(v.x));
            float ry = v.y - __bfloat162float(__float2bfloat16(v.y));
            float rz = v.z - __bfloat162float(__float2bfloat16(v.z));
            float rw = v.w - __bfloat162float(__float2bfloat16(v.w));
            uint32_t lo0 = pack_bf16(rx, ry);
            uint32_t lo1 = pack_bf16(rz, rw);
            *reinterpret_cast<uint2*>(dH + q * 8) = make_uint2(hi0, hi1);
            *reinterpret_cast<uint2*>(dL + q * 8) = make_uint2(lo0, lo1);
        }
    }
    __syncthreads();

    uint2* Bb0 = reinterpret_cast<uint2*>(smem + OFF_B0);
    uint2* Bb1 = reinterpret_cast<uint2*>(smem + OFF_B1);

    for (int h = 0; h < 2; h++) {
        float acc[2][8][4];
        #pragma unroll
        for (int t = 0; t < 2; t++)
            #pragma unroll
            for (int nt = 0; nt < 8; nt++)
                #pragma unroll
                for (int e = 0; e < 4; e++)
                    acc[t][nt][e] = 0.f;

        const uint2* gw = g_Wfrag + h * 16384;

        {
            const uint4* src = reinterpret_cast<const uint4*>(gw);
            uint4* dst = reinterpret_cast<uint4*>(Bb0);
            #pragma unroll
            for (int q = 0; q < 8; q++)
                dst[tid + q * 256] = src[tid + q * 256];
        }
        __syncthreads();

        for (int c = 0; c < 4; c++) {
            if (c < 3) {
                const uint4* src = reinterpret_cast<const uint4*>(
                    gw + (c + 1) * 4096);
                uint4* dst = reinterpret_cast<uint4*>((c & 1) ? Bb0 : Bb1);
                #pragma unroll
                for (int q = 0; q < 8; q++)
                    dst[tid + q * 256] = src[tid + q * 256];
            }
            const uint2* bb = (c & 1) ? Bb1 : Bb0;

            #pragma unroll
            for (int kk = 0; kk < 4; kk++) {
                int k16g = c * 4 + kk;
                uint32_t aH[2][4], aL[2][4];
                #pragma unroll
                for (int t = 0; t < 2; t++) {
                    uint32_t off = (uint32_t)(warpM * 32 + t * 16 + (lane & 15)) * 528
                                 + (uint32_t)k16g * 32 + (lane >> 4) * 16;
                    ldmatrix_x4(aH[t], sb + off);
                    ldmatrix_x4(aL[t], sb + OFF_AL + off);
                }
                #pragma unroll
                for (int nt = 0; nt < 8; nt++) {
                    int n8 = warpN * 8 + nt;
                    uint2 bH = bb[(kk * 2 + 0) * 512 + n8 * 32 + lane];
                    uint2 bL = bb[(kk * 2 + 1) * 512 + n8 * 32 + lane];
                    mma_bf16(acc[0][nt], aH[0], bH);
                    mma_bf16(acc[1][nt], aH[1], bH);
                    mma_bf16(acc[0][nt], aL[0], bH);
                    mma_bf16(acc[1][nt], aL[1], bH);
                    mma_bf16(acc[0][nt], aH[0], bL);
                    mma_bf16(acc[1][nt], aH[1], bL);
                }
            }
            __syncthreads();
        }

        #pragma unroll
        for (int t = 0; t < 2; t++) {
            #pragma unroll
            for (int nt = 0; nt < 8; nt++) {
                int row0 = rowBase + warpM * 32 + t * 16 + (lane >> 2);
                int col  = h * 128 + warpN * 64 + nt * 8 + (lane & 3) * 2;
                if (row0 < M)
                    *reinterpret_cast<float2*>(g_Y + (size_t)row0 * 256 + col) =
                        make_float2(acc[t][nt][0], acc[t][nt][1]);
                int row1 = row0 + 8;
                if (row1 < M)
                    *reinterpret_cast<float2*>(g_Y + (size_t)row1 * 256 + col) =
                        make_float2(acc[t][nt][2], acc[t][nt][3]);
            }
        }
        __syncthreads();
    }
}

// ---------------------------------------------------------------------------
// CSR build
// ---------------------------------------------------------------------------
__global__ void zero_cnt_kernel(int M) {
    int i = blockIdx.x * blockDim.x + threadIdx.x;
    if (i < M) g_cnt[i] = 0;
}

__global__ void hist_kernel(const int* __restrict__ erow, int E) {
    int i = blockIdx.x * blockDim.x + threadIdx.x;
    if (i < E) atomicAdd(&g_cnt[erow[i]], 1);
}

__global__ __launch_bounds__(SCAN_B)
void scan1_kernel(int M) {
    __shared__ int sh[SCAN_B];
    int tid = threadIdx.x;
    int i = blockIdx.x * SCAN_B + tid;
    int v = (i < M) ? g_cnt[i] : 0;
    sh[tid] = v;
    __syncthreads();
    #pragma unroll
    for (int d = 1; d < SCAN_B; d <<= 1) {
        int t = (tid >= d) ? sh[tid - d] : 0;
        __syncthreads();
        sh[tid] += t;
        __syncthreads();
    }
    if (i < M) g_off[i] = sh[tid] - v;
    if (tid == SCAN_B - 1) g_part[blockIdx.x] = sh[tid];
}

// scan2 merged into scan3: every block redundantly scans the <=128 partials.
__global__ __launch_bounds__(256)
void scan3_kernel(int M, int E, int nb) {
    __shared__ int sh[MAX_SCAN_BLOCKS];
    int tid = threadIdx.x;
    if (tid < MAX_SCAN_BLOCKS) {
        int v = (tid < nb) ? g_part[tid] : 0;
        sh[tid] = v;
    }
    __syncthreads();
    if (tid < MAX_SCAN_BLOCKS) {
        #pragma unroll
        for (int d = 1; d < MAX_SCAN_BLOCKS; d <<= 1) {
            int t = (tid >= d) ? sh[tid - d] : 0;
            __syncthreads();
            sh[tid] += t;
            __syncthreads();
        }
    } else {
        #pragma unroll
        for (int d = 1; d < MAX_SCAN_BLOCKS; d <<= 1) {
            __syncthreads();
            __syncthreads();
        }
    }
    // sh now holds inclusive scan; exclusive prefix for block b is sh[b-1]
    int i = blockIdx.x * blockDim.x + tid;
    if (i < M) {
        int b = i >> 10;
        int pre = (b == 0) ? 0 : sh[b - 1];
        int o = g_off[i] + pre;
        g_off[i] = o;
        g_cur[i] = o;
    }
    if (i == 0) g_off[M] = E;
}

__global__ void assign_kernel(const int* __restrict__ erow,
                              const int* __restrict__ ecol,
                              const float* __restrict__ eval, int E) {
    int i = blockIdx.x * blockDim.x + threadIdx.x;
    if (i < E) {
        int r = erow[i];
        int p = atomicAdd(&g_cur[r], 1);
        g_cv[p] = make_int2(ecol[i], __float_as_int(eval[i]));
    }
}

// ---------------------------------------------------------------------------
// SpMM over CSR: one warp per row; register accumulation, bias fused.
// ---------------------------------------------------------------------------
__global__ __launch_bounds__(256)
void spmm_csr_kernel(const float* __restrict__ bias,
                     float* __restrict__ out, int M) {
    int warp = (blockIdx.x * blockDim.x + threadIdx.x) >> 5;
    int lane = threadIdx.x & 31;
    if (warp >= M) return;

    int start = g_off[warp];
    int end   = g_off[warp + 1];

    float4 a0 = reinterpret_cast<const float4*>(bias)[lane * 2 + 0];
    float4 a1 = reinterpret_cast<const float4*>(bias)[lane * 2 + 1];

    for (int base = start; base < end; base += 32) {
        int idx = base + lane;
        int2 cvl = make_int2(0, 0);
        if (idx < end) cvl = g_cv[idx];
        int n = min(32, end - base);

        int j = 0;
        for (; j + 2 <= n; j += 2) {
            int   c0 = __shfl_sync(0xffffffffu, cvl.x, j);
            float v0 = __int_as_float(__shfl_sync(0xffffffffu, cvl.y, j));
            int   c1 = __shfl_sync(0xffffffffu, cvl.x, j + 1);
            float v1 = __int_as_float(__shfl_sync(0xffffffffu, cvl.y, j + 1));
            const float4* y0p = reinterpret_cast<const float4*>(
                g_Y + (size_t)c0 * DIM) + lane * 2;
            const float4* y1p = reinterpret_cast<const float4*>(
                g_Y + (size_t)c1 * DIM) + lane * 2;
            float4 y00 = __ldg(y0p + 0), y01 = __ldg(y0p + 1);
            float4 y10 = __ldg(y1p + 0), y11 = __ldg(y1p + 1);
            a0.x += v0 * y00.x; a0.y += v0 * y00.y; a0.z += v0 * y00.z; a0.w += v0 * y00.w;
            a1.x += v0 * y01.x; a1.y += v0 * y01.y; a1.z += v0 * y01.z; a1.w += v0 * y01.w;
            a0.x += v1 * y10.x; a0.y += v1 * y10.y; a0.z += v1 * y10.z; a0.w += v1 * y10.w;
            a1.x += v1 * y11.x; a1.y += v1 * y11.y; a1.z += v1 * y11.z; a1.w += v1 * y11.w;
        }
        if (j < n) {
            int   c0 = __shfl_sync(0xffffffffu, cvl.x, j);
            float v0 = __int_as_float(__shfl_sync(0xffffffffu, cvl.y, j));
            const float4* y0p = reinterpret_cast<const float4*>(
                g_Y + (size_t)c0 * DIM) + lane * 2;
            float4 y00 = __ldg(y0p + 0), y01 = __ldg(y0p + 1);
            a0.x += v0 * y00.x; a0.y += v0 * y00.y; a0.z += v0 * y00.z; a0.w += v0 * y00.w;
            a1.x += v0 * y01.x; a1.y += v0 * y01.y; a1.z += v0 * y01.z; a1.w += v0 * y01.w;
        }
    }

    float4* o = reinterpret_cast<float4*>(out + (size_t)warp * DIM) + lane * 2;
    o[0] = a0;
    o[1] = a1;
}

// ---------------------------------------------------------------------------
// Launch: fork CSR build onto a side stream so it overlaps the GEMM.
// Stream/events are created per call (only correctness + capture calls exist);
// they are host objects, not device memory. All ops are graph-capture legal.
// ---------------------------------------------------------------------------
extern "C" void kernel_launch(void* const* d_in, const int* in_sizes, int n_in,
                              void* d_out, int out_size) {
    const float* X    = (const float*)d_in[0];
    const int*   erow = (const int*)  d_in[1];
    const int*   ecol = (const int*)  d_in[2];
    const float* eval = (const float*)d_in[3];
    const float* W    = (const float*)d_in[4];
    const float* bias = (const float*)d_in[5];
    float* out = (float*)d_out;

    int M = in_sizes[0] / DIM;   // 100000
    int E = in_sizes[1];         // 1600000
    int nScanBlocks = (M + SCAN_B - 1) / SCAN_B;

    cudaFuncSetAttribute(gemm_tc_kernel,
                         cudaFuncAttributeMaxDynamicSharedMemorySize, GEMM_SMEM);

    cudaStream_t s2;
    cudaEvent_t evStart, evCsr;
    cudaStreamCreateWithFlags(&s2, cudaStreamNonBlocking);
    cudaEventCreateWithFlags(&evStart, cudaEventDisableTiming);
    cudaEventCreateWithFlags(&evCsr, cudaEventDisableTiming);

    // fork: s2 branches off the (captured) default stream
    cudaEventRecord(evStart, 0);
    cudaStreamWaitEvent(s2, evStart, 0);

    // branch A (s2): CSR build               // launch order overall:
    zero_cnt_kernel<<<(M + 255) / 256, 256, 0, s2>>>(M);            // #1
    hist_kernel<<<(E + 255) / 256, 256, 0, s2>>>(erow, E);          // #2

    // branch B (default): W prep + GEMM
    wprep_kernel<<<32768 / 256, 256>>>(W);                          // #3
    int nTiles = (M + 127) / 128;
    gemm_tc_kernel<<<nTiles, 256, GEMM_SMEM>>>(X, M);               // #4 <- ncu slot

    // branch A continued
    scan1_kernel<<<nScanBlocks, SCAN_B, 0, s2>>>(M);                // #5
    scan3_kernel<<<(M + 255) / 256, 256, 0, s2>>>(M, E, nScanBlocks); // #6
    assign_kernel<<<(E + 255) / 256, 256, 0, s2>>>(erow, ecol, eval, E); // #7

    // join: default stream waits for CSR branch
    cudaEventRecord(evCsr, s2);
    cudaStreamWaitEvent(0, evCsr, 0);

    // out[r] = bias + sum_e v * Y[c]
    int rows_per_block = 256 / 32;
    spmm_csr_kernel<<<(M + rows_per_block - 1) / rows_per_block, 256>>>(bias, out, M); // #8
}

// round 7
// speedup vs baseline: 1.1513x; 1.1513x over previous
#include <cuda_runtime.h>
#include <cuda_bf16.h>
#include <cstdint>

#define MAX_NODES 100032
#define MAX_EDGES 1600000
#define DIM 256
#define SCAN_B 1024
#define MAX_SCAN_BLOCKS 128

// Scratch (static device globals — no allocation allowed)
static __device__ float g_Y[(size_t)MAX_NODES * DIM];   // Y = X @ W
static __device__ int   g_cnt[MAX_NODES];
static __device__ int   g_off[MAX_NODES + 1];
static __device__ int   g_cur[MAX_NODES];
static __device__ int   g_part[MAX_SCAN_BLOCKS];
static __device__ int2  g_cv[MAX_EDGES];
// Pre-baked mma B fragments of W (bf16 hi/lo split), layout
// [h(2)][k16(16)][hl(2)][n8(16)][lane(32)] of uint2 {b0,b1} = 512 KB
static __device__ uint2 g_Wfrag[2 * 16 * 2 * 16 * 32];

// ---------------------------------------------------------------------------
// helpers
// ---------------------------------------------------------------------------
__device__ __forceinline__ void mma_bf16(float* d, const uint32_t* a, uint2 b) {
    asm volatile(
        "mma.sync.aligned.m16n8k16.row.col.f32.bf16.bf16.f32 "
        "{%0,%1,%2,%3}, {%4,%5,%6,%7}, {%8,%9}, {%0,%1,%2,%3};"
        : "+f"(d[0]), "+f"(d[1]), "+f"(d[2]), "+f"(d[3])
        : "r"(a[0]), "r"(a[1]), "r"(a[2]), "r"(a[3]), "r"(b.x), "r"(b.y));
}
__device__ __forceinline__ uint32_t pack_bf16(float a, float b) {
    __nv_bfloat16 ha = __float2bfloat16(a);
    __nv_bfloat16 hb = __float2bfloat16(b);
    return ((uint32_t)__bfloat16_as_ushort(hb) << 16) |
            (uint32_t)__bfloat16_as_ushort(ha);
}
__device__ __forceinline__ uint32_t pack_res(float2 v) {
    float rx = v.x - __bfloat162float(__float2bfloat16(v.x));
    float ry = v.y - __bfloat162float(__float2bfloat16(v.y));
    return pack_bf16(rx, ry);
}

// ---------------------------------------------------------------------------
// W prep: bf16 split + per-lane mma B-fragment bake.
// ---------------------------------------------------------------------------
__global__ void wprep_kernel(const float* __restrict__ W) {
    int i = blockIdx.x * blockDim.x + threadIdx.x;
    if (i >= 32768) return;
    int lane = i & 31;
    int n8   = (i >> 5) & 15;
    int hl   = (i >> 9) & 1;
    int k16  = (i >> 10) & 15;
    int h    = (i >> 14) & 1;
    int n  = h * 128 + n8 * 8 + (lane >> 2);
    int kb = k16 * 16 + (lane & 3) * 2;
    uint32_t r[2];
    #pragma unroll
    for (int reg = 0; reg < 2; reg++) {
        int k0 = kb + reg * 8;
        float f0 = W[(size_t)k0 * 256 + n];
        float f1 = W[(size_t)(k0 + 1) * 256 + n];
        if (hl == 0) {
            r[reg] = pack_bf16(f0, f1);
        } else {
            float h0 = __bfloat162float(__float2bfloat16(f0));
            float h1 = __bfloat162float(__float2bfloat16(f1));
            r[reg] = pack_bf16(f0 - h0, f1 - h1);
        }
    }
    g_Wfrag[i] = make_uint2(r[0], r[1]);
}

// ---------------------------------------------------------------------------
// HMMA GEMM, smem-free: all operands straight from global (L1/L2 cached).
// CTA = 128 rows x 128 cols (blockIdx.y = N-half). 8 warps: 4M x 2N,
// warp tile 32x64. A fragments built inline (bf16 hi/lo split) from X.
// No shared memory, no __syncthreads -> 2 CTAs/SM, 16 warps.
// ---------------------------------------------------------------------------
__global__ __launch_bounds__(256, 2)
void gemm_tc_kernel(const float* __restrict__ X, int M) {
    const int tid   = threadIdx.x;
    const int lane  = tid & 31;
    const int wid   = tid >> 5;
    const int warpM = wid & 3;
    const int warpN = wid >> 2;
    const int h     = blockIdx.y;
    const int rowBase = blockIdx.x * 128;

    const int r0 = rowBase + warpM * 32 + (lane >> 2);
    const int c0 = (lane & 3) * 2;

    float acc[2][8][4];
    #pragma unroll
    for (int t = 0; t < 2; t++)
        #pragma unroll
        for (int nt = 0; nt < 8; nt++)
            #pragma unroll
            for (int e = 0; e < 4; e++)
                acc[t][nt][e] = 0.f;

    const uint2* __restrict__ wf = g_Wfrag + (size_t)h * 16384
                                 + (size_t)warpN * 8 * 32 + lane;

    #pragma unroll 2
    for (int k16 = 0; k16 < 16; k16++) {
        uint32_t aH[2][4], aL[2][4];
        const int col = k16 * 16 + c0;
        #pragma unroll
        for (int t = 0; t < 2; t++) {
            int ra = r0 + t * 16;
            int rb = ra + 8;
            float2 z = make_float2(0.f, 0.f);
            float2 f00 = (ra < M) ? __ldg((const float2*)(X + (size_t)ra * 256 + col))     : z;
            float2 f01 = (ra < M) ? __ldg((const float2*)(X + (size_t)ra * 256 + col + 8)) : z;
            float2 f10 = (rb < M) ? __ldg((const float2*)(X + (size_t)rb * 256 + col))     : z;
            float2 f11 = (rb < M) ? __ldg((const float2*)(X + (size_t)rb * 256 + col + 8)) : z;
            aH[t][0] = pack_bf16(f00.x, f00.y);
            aH[t][1] = pack_bf16(f10.x, f10.y);
            aH[t][2] = pack_bf16(f01.x, f01.y);
            aH[t][3] = pack_bf16(f11.x, f11.y);
            aL[t][0] = pack_res(f00);
            aL[t][1] = pack_res(f10);
            aL[t][2] = pack_res(f01);
            aL[t][3] = pack_res(f11);
        }
        const uint2* bp = wf + (size_t)(k16 * 2) * 512;
        #pragma unroll
        for (int nt = 0; nt < 8; nt++) {
            uint2 bH = __ldg(bp + nt * 32);
            uint2 bL = __ldg(bp + nt * 32 + 512);
            mma_bf16(acc[0][nt], aH[0], bH);
            mma_bf16(acc[1][nt], aH[1], bH);
            mma_bf16(acc[0][nt], aL[0], bH);
            mma_bf16(acc[1][nt], aL[1], bH);
            mma_bf16(acc[0][nt], aH[0], bL);
            mma_bf16(acc[1][nt], aH[1], bL);
        }
    }

    // epilogue: direct coalesced v2 stores
    #pragma unroll
    for (int t = 0; t < 2; t++) {
        #pragma unroll
        for (int nt = 0; nt < 8; nt++) {
            int row0 = rowBase + warpM * 32 + t * 16 + (lane >> 2);
            int col  = h * 128 + warpN * 64 + nt * 8 + (lane & 3) * 2;
            if (row0 < M)
                *reinterpret_cast<float2*>(g_Y + (size_t)row0 * 256 + col) =
                    make_float2(acc[t][nt][0], acc[t][nt][1]);
            int row1 = row0 + 8;
            if (row1 < M)
                *reinterpret_cast<float2*>(g_Y + (size_t)row1 * 256 + col) =
                    make_float2(acc[t][nt][2], acc[t][nt][3]);
        }
    }
}

// ---------------------------------------------------------------------------
// CSR build
// ---------------------------------------------------------------------------
__global__ void zero_cnt_kernel(int M) {
    int i = blockIdx.x * blockDim.x + threadIdx.x;
    if (i < M) g_cnt[i] = 0;
}

__global__ void hist_kernel(const int* __restrict__ erow, int E) {
    int i = blockIdx.x * blockDim.x + threadIdx.x;
    if (i < E) atomicAdd(&g_cnt[erow[i]], 1);
}

__global__ __launch_bounds__(SCAN_B)
void scan1_kernel(int M) {
    __shared__ int sh[SCAN_B];
    int tid = threadIdx.x;
    int i = blockIdx.x * SCAN_B + tid;
    int v = (i < M) ? g_cnt[i] : 0;
    sh[tid] = v;
    __syncthreads();
    #pragma unroll
    for (int d = 1; d < SCAN_B; d <<= 1) {
        int t = (tid >= d) ? sh[tid - d] : 0;
        __syncthreads();
        sh[tid] += t;
        __syncthreads();
    }
    if (i < M) g_off[i] = sh[tid] - v;
    if (tid == SCAN_B - 1) g_part[blockIdx.x] = sh[tid];
}

// scan2 merged into scan3: every block redundantly scans the <=128 partials.
__global__ __launch_bounds__(256)
void scan3_kernel(int M, int E, int nb) {
    __shared__ int sh[MAX_SCAN_BLOCKS];
    int tid = threadIdx.x;
    if (tid < MAX_SCAN_BLOCKS) {
        int v = (tid < nb) ? g_part[tid] : 0;
        sh[tid] = v;
    }
    __syncthreads();
    if (tid < MAX_SCAN_BLOCKS) {
        #pragma unroll
        for (int d = 1; d < MAX_SCAN_BLOCKS; d <<= 1) {
            int t = (tid >= d) ? sh[tid - d] : 0;
            __syncthreads();
            sh[tid] += t;
            __syncthreads();
        }
    } else {
        #pragma unroll
        for (int d = 1; d < MAX_SCAN_BLOCKS; d <<= 1) {
            __syncthreads();
            __syncthreads();
        }
    }
    int i = blockIdx.x * blockDim.x + tid;
    if (i < M) {
        int b = i >> 10;
        int pre = (b == 0) ? 0 : sh[b - 1];
        int o = g_off[i] + pre;
        g_off[i] = o;
        g_cur[i] = o;
    }
    if (i == 0) g_off[M] = E;
}

__global__ void assign_kernel(const int* __restrict__ erow,
                              const int* __restrict__ ecol,
                              const float* __restrict__ eval, int E) {
    int i = blockIdx.x * blockDim.x + threadIdx.x;
    if (i < E) {
        int r = erow[i];
        int p = atomicAdd(&g_cur[r], 1);
        g_cv[p] = make_int2(ecol[i], __float_as_int(eval[i]));
    }
}

// ---------------------------------------------------------------------------
// SpMM over CSR: one warp per row; register accumulation, bias fused.
// ---------------------------------------------------------------------------
__global__ __launch_bounds__(256)
void spmm_csr_kernel(const float* __restrict__ bias,
                     float* __restrict__ out, int M) {
    int warp = (blockIdx.x * blockDim.x + threadIdx.x) >> 5;
    int lane = threadIdx.x & 31;
    if (warp >= M) return;

    int start = g_off[warp];
    int end   = g_off[warp + 1];

    float4 a0 = reinterpret_cast<const float4*>(bias)[lane * 2 + 0];
    float4 a1 = reinterpret_cast<const float4*>(bias)[lane * 2 + 1];

    for (int base = start; base < end; base += 32) {
        int idx = base + lane;
        int2 cvl = make_int2(0, 0);
        if (idx < end) cvl = g_cv[idx];
        int n = min(32, end - base);

        int j = 0;
        for (; j + 2 <= n; j += 2) {
            int   c0 = __shfl_sync(0xffffffffu, cvl.x, j);
            float v0 = __int_as_float(__shfl_sync(0xffffffffu, cvl.y, j));
            int   c1 = __shfl_sync(0xffffffffu, cvl.x, j + 1);
            float v1 = __int_as_float(__shfl_sync(0xffffffffu, cvl.y, j + 1));
            const float4* y0p = reinterpret_cast<const float4*>(
                g_Y + (size_t)c0 * DIM) + lane * 2;
            const float4* y1p = reinterpret_cast<const float4*>(
                g_Y + (size_t)c1 * DIM) + lane * 2;
            float4 y00 = __ldg(y0p + 0), y01 = __ldg(y0p + 1);
            float4 y10 = __ldg(y1p + 0), y11 = __ldg(y1p + 1);
            a0.x += v0 * y00.x; a0.y += v0 * y00.y; a0.z += v0 * y00.z; a0.w += v0 * y00.w;
            a1.x += v0 * y01.x; a1.y += v0 * y01.y; a1.z += v0 * y01.z; a1.w += v0 * y01.w;
            a0.x += v1 * y10.x; a0.y += v1 * y10.y; a0.z += v1 * y10.z; a0.w += v1 * y10.w;
            a1.x += v1 * y11.x; a1.y += v1 * y11.y; a1.z += v1 * y11.z; a1.w += v1 * y11.w;
        }
        if (j < n) {
            int   c0 = __shfl_sync(0xffffffffu, cvl.x, j);
            float v0 = __int_as_float(__shfl_sync(0xffffffffu, cvl.y, j));
            const float4* y0p = reinterpret_cast<const float4*>(
                g_Y + (size_t)c0 * DIM) + lane * 2;
            float4 y00 = __ldg(y0p + 0), y01 = __ldg(y0p + 1);
            a0.x += v0 * y00.x; a0.y += v0 * y00.y; a0.z += v0 * y00.z; a0.w += v0 * y00.w;
            a1.x += v0 * y01.x; a1.y += v0 * y01.y; a1.z += v0 * y01.z; a1.w += v0 * y01.w;
        }
    }

    float4* o = reinterpret_cast<float4*>(out + (size_t)warp * DIM) + lane * 2;
    o[0] = a0;
    o[1] = a1;
}

// ---------------------------------------------------------------------------
// Launch: fork CSR build onto a side stream so it overlaps the GEMM.
// ---------------------------------------------------------------------------
extern "C" void kernel_launch(void* const* d_in, const int* in_sizes, int n_in,
                              void* d_out, int out_size) {
    const float* X    = (const float*)d_in[0];
    const int*   erow = (const int*)  d_in[1];
    const int*   ecol = (const int*)  d_in[2];
    const float* eval = (const float*)d_in[3];
    const float* W    = (const float*)d_in[4];
    const float* bias = (const float*)d_in[5];
    float* out = (float*)d_out;

    int M = in_sizes[0] / DIM;   // 100000
    int E = in_sizes[1];         // 1600000
    int nScanBlocks = (M + SCAN_B - 1) / SCAN_B;

    cudaStream_t s2;
    cudaEvent_t evStart, evCsr;
    cudaStreamCreateWithFlags(&s2, cudaStreamNonBlocking);
    cudaEventCreateWithFlags(&evStart, cudaEventDisableTiming);
    cudaEventCreateWithFlags(&evCsr, cudaEventDisableTiming);

    // fork: s2 branches off the (captured) default stream
    cudaEventRecord(evStart, 0);
    cudaStreamWaitEvent(s2, evStart, 0);

    // branch A (s2): CSR build               // launch order overall:
    zero_cnt_kernel<<<(M + 255) / 256, 256, 0, s2>>>(M);            // #1
    hist_kernel<<<(E + 255) / 256, 256, 0, s2>>>(erow, E);          // #2

    // branch B (default): W prep + GEMM
    wprep_kernel<<<32768 / 256, 256>>>(W);                          // #3
    int nTiles = (M + 127) / 128;
    gemm_tc_kernel<<<dim3(nTiles, 2), 256>>>(X, M);                 // #4 <- ncu slot

    // branch A continued
    scan1_kernel<<<nScanBlocks, SCAN_B, 0, s2>>>(M);                // #5
    scan3_kernel<<<(M + 255) / 256, 256, 0, s2>>>(M, E, nScanBlocks); // #6
    assign_kernel<<<(E + 255) / 256, 256, 0, s2>>>(erow, ecol, eval, E); // #7

    // join: default stream waits for CSR branch
    cudaEventRecord(evCsr, s2);
    cudaStreamWaitEvent(0, evCsr, 0);

    // out[r] = bias + sum_e v * Y[c]
    int rows_per_block = 256 / 32;
    spmm_csr_kernel<<<(M + rows_per_block - 1) / rows_per_block, 256>>>(bias, out, M); // #8
}

// round 8
// speedup vs baseline: 1.4027x; 1.2184x over previous
#include <cuda_runtime.h>
#include <cuda_bf16.h>
#include <cuda_fp16.h>
#include <cstdint>

#define MAX_NODES 100032
#define MAX_EDGES 1600000
#define DIM 256
#define SCAN_B 1024
#define MAX_SCAN_BLOCKS 128

// Scratch (static device globals — no allocation allowed)
static __device__ __half g_Yh[(size_t)MAX_NODES * DIM];  // Y = X @ W (fp16)
static __device__ int   g_cnt[MAX_NODES];
static __device__ int   g_off[MAX_NODES + 1];
static __device__ int   g_cur[MAX_NODES];
static __device__ int   g_part[MAX_SCAN_BLOCKS];
static __device__ int2  g_cv[MAX_EDGES];
// Pre-baked mma B fragments of W, interleaved hi/lo:
// [h(2)][k16(16)][n8(16)][lane(32)] of uint4 {bH.x,bH.y,bL.x,bL.y} = 256 KB
static __device__ uint4 g_Wfrag[2 * 16 * 16 * 32];

// ---------------------------------------------------------------------------
// helpers
// ---------------------------------------------------------------------------
__device__ __forceinline__ void mma_bf16(float* d, const uint32_t* a,
                                         uint32_t b0, uint32_t b1) {
    asm volatile(
        "mma.sync.aligned.m16n8k16.row.col.f32.bf16.bf16.f32 "
        "{%0,%1,%2,%3}, {%4,%5,%6,%7}, {%8,%9}, {%0,%1,%2,%3};"
        : "+f"(d[0]), "+f"(d[1]), "+f"(d[2]), "+f"(d[3])
        : "r"(a[0]), "r"(a[1]), "r"(a[2]), "r"(a[3]), "r"(b0), "r"(b1));
}
__device__ __forceinline__ uint32_t pack_bf16(float a, float b) {
    __nv_bfloat16 ha = __float2bfloat16(a);
    __nv_bfloat16 hb = __float2bfloat16(b);
    return ((uint32_t)__bfloat16_as_ushort(hb) << 16) |
            (uint32_t)__bfloat16_as_ushort(ha);
}
__device__ __forceinline__ uint32_t pack_res(float x, float y) {
    float rx = x - __bfloat162float(__float2bfloat16(x));
    float ry = y - __bfloat162float(__float2bfloat16(y));
    return pack_bf16(rx, ry);
}
__device__ __forceinline__ uint32_t pack_res2(float2 v) { return pack_res(v.x, v.y); }

// ---------------------------------------------------------------------------
// W prep: bf16 split + per-lane mma B-fragment bake (hi/lo interleaved uint4)
// ---------------------------------------------------------------------------
__global__ void wprep_kernel(const float* __restrict__ W) {
    int i = blockIdx.x * blockDim.x + threadIdx.x;
    if (i >= 16384) return;
    int lane = i & 31;
    int n8   = (i >> 5) & 15;
    int k16  = (i >> 9) & 15;
    int h    = (i >> 13) & 1;
    int n  = h * 128 + n8 * 8 + (lane >> 2);
    int kb = k16 * 16 + (lane & 3) * 2;
    float f0 = W[(size_t)kb * 256 + n];
    float f1 = W[(size_t)(kb + 1) * 256 + n];
    float g0 = W[(size_t)(kb + 8) * 256 + n];
    float g1 = W[(size_t)(kb + 9) * 256 + n];
    uint4 o;
    o.x = pack_bf16(f0, f1);
    o.y = pack_bf16(g0, g1);
    o.z = pack_res(f0, f1);
    o.w = pack_res(g0, g1);
    g_Wfrag[i] = o;
}

// ---------------------------------------------------------------------------
// HMMA GEMM, smem-free: operands straight from global (L1/L2 cached).
// CTA = 128 rows x 128 cols (blockIdx.y = N-half). 8 warps: 4M x 2N.
// bf16 3-product split (XhWh + XlWh + XhWl). Y stored fp16.
// ---------------------------------------------------------------------------
__global__ __launch_bounds__(256, 2)
void gemm_tc_kernel(const float* __restrict__ X, int M) {
    const int lane  = threadIdx.x & 31;
    const int wid   = threadIdx.x >> 5;
    const int warpM = wid & 3;
    const int warpN = wid >> 2;
    const int h     = blockIdx.y;
    const int rowBase = blockIdx.x * 128;

    const int r0 = rowBase + warpM * 32 + (lane >> 2);
    const int c0 = (lane & 3) * 2;

    float acc[2][8][4];
    #pragma unroll
    for (int t = 0; t < 2; t++)
        #pragma unroll
        for (int nt = 0; nt < 8; nt++)
            #pragma unroll
            for (int e = 0; e < 4; e++)
                acc[t][nt][e] = 0.f;

    const uint4* __restrict__ wf = g_Wfrag
        + ((size_t)h * 16 * 16 + (size_t)warpN * 8) * 32 + lane;

    #pragma unroll 2
    for (int k16 = 0; k16 < 16; k16++) {
        uint32_t aH[2][4], aL[2][4];
        const int col = k16 * 16 + c0;
        #pragma unroll
        for (int t = 0; t < 2; t++) {
            int ra = r0 + t * 16;
            int rb = ra + 8;
            float2 z = make_float2(0.f, 0.f);
            float2 f00 = (ra < M) ? __ldg((const float2*)(X + (size_t)ra * 256 + col))     : z;
            float2 f01 = (ra < M) ? __ldg((const float2*)(X + (size_t)ra * 256 + col + 8)) : z;
            float2 f10 = (rb < M) ? __ldg((const float2*)(X + (size_t)rb * 256 + col))     : z;
            float2 f11 = (rb < M) ? __ldg((const float2*)(X + (size_t)rb * 256 + col + 8)) : z;
            aH[t][0] = pack_bf16(f00.x, f00.y);
            aH[t][1] = pack_bf16(f10.x, f10.y);
            aH[t][2] = pack_bf16(f01.x, f01.y);
            aH[t][3] = pack_bf16(f11.x, f11.y);
            aL[t][0] = pack_res2(f00);
            aL[t][1] = pack_res2(f10);
            aL[t][2] = pack_res2(f01);
            aL[t][3] = pack_res2(f11);
        }
        const uint4* bp = wf + (size_t)(k16 * 16) * 32;
        #pragma unroll
        for (int nt = 0; nt < 8; nt++) {
            uint4 b = __ldg(bp + nt * 32);
            mma_bf16(acc[0][nt], aH[0], b.x, b.y);
            mma_bf16(acc[1][nt], aH[1], b.x, b.y);
            mma_bf16(acc[0][nt], aL[0], b.x, b.y);
            mma_bf16(acc[1][nt], aL[1], b.x, b.y);
            mma_bf16(acc[0][nt], aH[0], b.z, b.w);
            mma_bf16(acc[1][nt], aH[1], b.z, b.w);
        }
    }

    // epilogue: fp16 stores
    #pragma unroll
    for (int t = 0; t < 2; t++) {
        #pragma unroll
        for (int nt = 0; nt < 8; nt++) {
            int row0 = rowBase + warpM * 32 + t * 16 + (lane >> 2);
            int col  = h * 128 + warpN * 64 + nt * 8 + (lane & 3) * 2;
            if (row0 < M)
                *reinterpret_cast<__half2*>(g_Yh + (size_t)row0 * 256 + col) =
                    __floats2half2_rn(acc[t][nt][0], acc[t][nt][1]);
            int row1 = row0 + 8;
            if (row1 < M)
                *reinterpret_cast<__half2*>(g_Yh + (size_t)row1 * 256 + col) =
                    __floats2half2_rn(acc[t][nt][2], acc[t][nt][3]);
        }
    }
}

// ---------------------------------------------------------------------------
// CSR build
// ---------------------------------------------------------------------------
__global__ void zero_cnt_kernel(int M) {
    int i = blockIdx.x * blockDim.x + threadIdx.x;
    if (i < M) g_cnt[i] = 0;
}

__global__ void hist_kernel(const int* __restrict__ erow, int E) {
    int i = blockIdx.x * blockDim.x + threadIdx.x;
    if (i < E) atomicAdd(&g_cnt[erow[i]], 1);
}

__global__ __launch_bounds__(SCAN_B)
void scan1_kernel(int M) {
    __shared__ int sh[SCAN_B];
    int tid = threadIdx.x;
    int i = blockIdx.x * SCAN_B + tid;
    int v = (i < M) ? g_cnt[i] : 0;
    sh[tid] = v;
    __syncthreads();
    #pragma unroll
    for (int d = 1; d < SCAN_B; d <<= 1) {
        int t = (tid >= d) ? sh[tid - d] : 0;
        __syncthreads();
        sh[tid] += t;
        __syncthreads();
    }
    if (i < M) g_off[i] = sh[tid] - v;
    if (tid == SCAN_B - 1) g_part[blockIdx.x] = sh[tid];
}

__global__ __launch_bounds__(256)
void scan3_kernel(int M, int E, int nb) {
    __shared__ int sh[MAX_SCAN_BLOCKS];
    int tid = threadIdx.x;
    if (tid < MAX_SCAN_BLOCKS) {
        int v = (tid < nb) ? g_part[tid] : 0;
        sh[tid] = v;
    }
    __syncthreads();
    if (tid < MAX_SCAN_BLOCKS) {
        #pragma unroll
        for (int d = 1; d < MAX_SCAN_BLOCKS; d <<= 1) {
            int t = (tid >= d) ? sh[tid - d] : 0;
            __syncthreads();
            sh[tid] += t;
            __syncthreads();
        }
    } else {
        #pragma unroll
        for (int d = 1; d < MAX_SCAN_BLOCKS; d <<= 1) {
            __syncthreads();
            __syncthreads();
        }
    }
    int i = blockIdx.x * blockDim.x + tid;
    if (i < M) {
        int b = i >> 10;
        int pre = (b == 0) ? 0 : sh[b - 1];
        int o = g_off[i] + pre;
        g_off[i] = o;
        g_cur[i] = o;
    }
    if (i == 0) g_off[M] = E;
}

__global__ void assign_kernel(const int* __restrict__ erow,
                              const int* __restrict__ ecol,
                              const float* __restrict__ eval, int E) {
    int i = blockIdx.x * blockDim.x + threadIdx.x;
    if (i < E) {
        int r = erow[i];
        int p = atomicAdd(&g_cur[r], 1);
        g_cv[p] = make_int2(ecol[i], __float_as_int(eval[i]));
    }
}

// ---------------------------------------------------------------------------
// SpMM over CSR: one warp per row; fp16 Y gather (one LDG.128 = 8 halves per
// lane per edge), fp32 register accumulation, bias fused.
// ---------------------------------------------------------------------------
__device__ __forceinline__ void acc_edge(float* a, uint4 y, float v) {
    float2 f;
    f = __half22float2(*reinterpret_cast<__half2*>(&y.x));
    a[0] += v * f.x; a[1] += v * f.y;
    f = __half22float2(*reinterpret_cast<__half2*>(&y.y));
    a[2] += v * f.x; a[3] += v * f.y;
    f = __half22float2(*reinterpret_cast<__half2*>(&y.z));
    a[4] += v * f.x; a[5] += v * f.y;
    f = __half22float2(*reinterpret_cast<__half2*>(&y.w));
    a[6] += v * f.x; a[7] += v * f.y;
}

__global__ __launch_bounds__(256)
void spmm_csr_kernel(const float* __restrict__ bias,
                     float* __restrict__ out, int M) {
    int warp = (blockIdx.x * blockDim.x + threadIdx.x) >> 5;
    int lane = threadIdx.x & 31;
    if (warp >= M) return;

    int start = g_off[warp];
    int end   = g_off[warp + 1];

    float a[8];
    {
        float4 b0 = reinterpret_cast<const float4*>(bias)[lane * 2 + 0];
        float4 b1 = reinterpret_cast<const float4*>(bias)[lane * 2 + 1];
        a[0] = b0.x; a[1] = b0.y; a[2] = b0.z; a[3] = b0.w;
        a[4] = b1.x; a[5] = b1.y; a[6] = b1.z; a[7] = b1.w;
    }

    for (int base = start; base < end; base += 32) {
        int idx = base + lane;
        int2 cvl = make_int2(0, 0);
        if (idx < end) cvl = g_cv[idx];
        int n = min(32, end - base);

        int j = 0;
        for (; j + 2 <= n; j += 2) {
            int   c0 = __shfl_sync(0xffffffffu, cvl.x, j);
            float v0 = __int_as_float(__shfl_sync(0xffffffffu, cvl.y, j));
            int   c1 = __shfl_sync(0xffffffffu, cvl.x, j + 1);
            float v1 = __int_as_float(__shfl_sync(0xffffffffu, cvl.y, j + 1));
            uint4 y0 = __ldg(reinterpret_cast<const uint4*>(
                g_Yh + (size_t)c0 * DIM) + lane);
            uint4 y1 = __ldg(reinterpret_cast<const uint4*>(
                g_Yh + (size_t)c1 * DIM) + lane);
            acc_edge(a, y0, v0);
            acc_edge(a, y1, v1);
        }
        if (j < n) {
            int   c0 = __shfl_sync(0xffffffffu, cvl.x, j);
            float v0 = __int_as_float(__shfl_sync(0xffffffffu, cvl.y, j));
            uint4 y0 = __ldg(reinterpret_cast<const uint4*>(
                g_Yh + (size_t)c0 * DIM) + lane);
            acc_edge(a, y0, v0);
        }
    }

    float4* o = reinterpret_cast<float4*>(out + (size_t)warp * DIM) + lane * 2;
    o[0] = make_float4(a[0], a[1], a[2], a[3]);
    o[1] = make_float4(a[4], a[5], a[6], a[7]);
}

// ---------------------------------------------------------------------------
// Launch: fork CSR build onto a side stream so it overlaps the GEMM.
// ---------------------------------------------------------------------------
extern "C" void kernel_launch(void* const* d_in, const int* in_sizes, int n_in,
                              void* d_out, int out_size) {
    const float* X    = (const float*)d_in[0];
    const int*   erow = (const int*)  d_in[1];
    const int*   ecol = (const int*)  d_in[2];
    const float* eval = (const float*)d_in[3];
    const float* W    = (const float*)d_in[4];
    const float* bias = (const float*)d_in[5];
    float* out = (float*)d_out;

    int M = in_sizes[0] / DIM;   // 100000
    int E = in_sizes[1];         // 1600000
    int nScanBlocks = (M + SCAN_B - 1) / SCAN_B;

    cudaStream_t s2;
    cudaEvent_t evStart, evCsr;
    cudaStreamCreateWithFlags(&s2, cudaStreamNonBlocking);
    cudaEventCreateWithFlags(&evStart, cudaEventDisableTiming);
    cudaEventCreateWithFlags(&evCsr, cudaEventDisableTiming);

    cudaEventRecord(evStart, 0);
    cudaStreamWaitEvent(s2, evStart, 0);

    // branch A (s2): CSR build               // launch order overall:
    zero_cnt_kernel<<<(M + 255) / 256, 256, 0, s2>>>(M);            // #1
    hist_kernel<<<(E + 255) / 256, 256, 0, s2>>>(erow, E);          // #2

    // branch B (default): W prep + GEMM
    wprep_kernel<<<16384 / 256, 256>>>(W);                          // #3
    int nTiles = (M + 127) / 128;
    gemm_tc_kernel<<<dim3(nTiles, 2), 256>>>(X, M);                 // #4 <- ncu slot

    // branch A continued
    scan1_kernel<<<nScanBlocks, SCAN_B, 0, s2>>>(M);                // #5
    scan3_kernel<<<(M + 255) / 256, 256, 0, s2>>>(M, E, nScanBlocks); // #6
    assign_kernel<<<(E + 255) / 256, 256, 0, s2>>>(erow, ecol, eval, E); // #7

    // join
    cudaEventRecord(evCsr, s2);
    cudaStreamWaitEvent(0, evCsr, 0);

    // out[r] = bias + sum_e v * Y[c]
    int rows_per_block = 256 / 32;
    spmm_csr_kernel<<<(M + rows_per_block - 1) / rows_per_block, 256>>>(bias, out, M); // #8
}

// round 10
// speedup vs baseline: 1.5176x; 1.0819x over previous
#include <cuda_runtime.h>
#include <cuda_bf16.h>
#include <cuda_fp16.h>
#include <cstdint>

#define DIM 256
#define MAX_TILES 6256                    // 782 blocks * 8 row16-tiles
#define MAX_NODES (MAX_TILES * 16)        // 100096
#define MAX_EDGES 1600000
#define SCAN_B 1024
#define MAX_SCAN_BLOCKS 128

// Scratch (static device globals — no allocation allowed)
static __device__ __half g_Yh[(size_t)MAX_NODES * DIM];       // Y = X @ W (fp16)
static __device__ int    g_cnt[MAX_NODES];
static __device__ int    g_off[MAX_NODES + 1];
static __device__ int    g_cur[MAX_NODES];
static __device__ int    g_part[MAX_SCAN_BLOCKS];
static __device__ int2   g_cv[MAX_EDGES];
// A fragments of X, fp16 hi/lo split: [tile][k16][hl][lane] uint4  (102 MB)
static __device__ uint4  g_Xfrag[(size_t)MAX_TILES * 16 * 2 * 32];
// B fragments of W (fp16): [h][k16][n8][lane] uint2  (128 KB)
static __device__ uint2  g_Wfrag[2 * 16 * 16 * 32];

// ---------------------------------------------------------------------------
// helpers
// ---------------------------------------------------------------------------
__device__ __forceinline__ void mma_f16(float* d, const uint32_t* a, uint2 b) {
    asm volatile(
        "mma.sync.aligned.m16n8k16.row.col.f32.f16.f16.f32 "
        "{%0,%1,%2,%3}, {%4,%5,%6,%7}, {%8,%9}, {%0,%1,%2,%3};"
        : "+f"(d[0]), "+f"(d[1]), "+f"(d[2]), "+f"(d[3])
        : "r"(a[0]), "r"(a[1]), "r"(a[2]), "r"(a[3]), "r"(b.x), "r"(b.y));
}
__device__ __forceinline__ uint32_t pack_h2(float a, float b) {
    __half2 h = __floats2half2_rn(a, b);
    return *reinterpret_cast<uint32_t*>(&h);
}
__device__ __forceinline__ uint32_t pack_h2res(float2 v, uint32_t hi) {
    __half2 hh = *reinterpret_cast<__half2*>(&hi);
    float2 f = __half22float2(hh);
    return pack_h2(v.x - f.x, v.y - f.y);
}

// ---------------------------------------------------------------------------
// W prep: fp16 per-lane mma B-fragment bake.
// ---------------------------------------------------------------------------
__global__ void wprep_kernel(const float* __restrict__ W) {
    int i = blockIdx.x * blockDim.x + threadIdx.x;
    if (i >= 16384) return;
    int lane = i & 31;
    int n8   = (i >> 5) & 15;
    int k16  = (i >> 9) & 15;
    int h    = (i >> 13) & 1;
    int n  = h * 128 + n8 * 8 + (lane >> 2);
    int kb = k16 * 16 + (lane & 3) * 2;
    uint2 o;
    o.x = pack_h2(W[(size_t)kb * 256 + n],       W[(size_t)(kb + 1) * 256 + n]);
    o.y = pack_h2(W[(size_t)(kb + 8) * 256 + n], W[(size_t)(kb + 9) * 256 + n]);
    g_Wfrag[i] = o;
}

// ---------------------------------------------------------------------------
// X prep: fp16 hi/lo split, baked into per-lane mma A-fragments.
// ---------------------------------------------------------------------------
__global__ __launch_bounds__(256)
void xprep_kernel(const float* __restrict__ X, int M) {
    int i = blockIdx.x * blockDim.x + threadIdx.x;   // MAX_TILES*16*32 threads
    int lane = i & 31;
    int k16  = (i >> 5) & 15;
    int tile = i >> 9;
    if (tile >= MAX_TILES) return;

    int r0 = tile * 16 + (lane >> 2);
    int r1 = r0 + 8;
    int col = k16 * 16 + (lane & 3) * 2;
    float2 z = make_float2(0.f, 0.f);
    float2 f00 = (r0 < M) ? __ldg((const float2*)(X + (size_t)r0 * 256 + col))     : z;
    float2 f01 = (r0 < M) ? __ldg((const float2*)(X + (size_t)r0 * 256 + col + 8)) : z;
    float2 f10 = (r1 < M) ? __ldg((const float2*)(X + (size_t)r1 * 256 + col))     : z;
    float2 f11 = (r1 < M) ? __ldg((const float2*)(X + (size_t)r1 * 256 + col + 8)) : z;

    uint4 aH, aL;
    aH.x = pack_h2(f00.x, f00.y);
    aH.y = pack_h2(f10.x, f10.y);
    aH.z = pack_h2(f01.x, f01.y);
    aH.w = pack_h2(f11.x, f11.y);
    aL.x = pack_h2res(f00, aH.x);
    aL.y = pack_h2res(f10, aH.y);
    aL.z = pack_h2res(f01, aH.z);
    aL.w = pack_h2res(f11, aH.w);

    size_t base = ((size_t)(tile * 16 + k16) * 2) * 32 + lane;
    g_Xfrag[base]      = aH;
    g_Xfrag[base + 32] = aL;
}

// ---------------------------------------------------------------------------
// HMMA GEMM (fp16 2-product split), smem-free, pre-baked fragments.
// blockIdx.y = N-half. CTA = 128 rows x 128 cols. 8 warps: 4M x 2N.
// ---------------------------------------------------------------------------
__global__ __launch_bounds__(256, 2)
void gemm_tc_kernel(int M) {
    const int lane  = threadIdx.x & 31;
    const int wid   = threadIdx.x >> 5;
    const int warpM = wid & 3;
    const int warpN = wid >> 2;
    const int h     = blockIdx.y;
    const int rowBase = blockIdx.x * 128;
    const int tile0 = blockIdx.x * 8 + warpM * 2;

    float acc[2][8][4];
    #pragma unroll
    for (int t = 0; t < 2; t++)
        #pragma unroll
        for (int nt = 0; nt < 8; nt++)
            #pragma unroll
            for (int e = 0; e < 4; e++)
                acc[t][nt][e] = 0.f;

    const uint2* __restrict__ wf = g_Wfrag
        + (((size_t)h * 16) * 16 + (size_t)warpN * 8) * 32 + lane;

    #pragma unroll 2
    for (int k16 = 0; k16 < 16; k16++) {
        uint4 aH[2], aL[2];
        #pragma unroll
        for (int t = 0; t < 2; t++) {
            size_t base = ((size_t)((tile0 + t) * 16 + k16) * 2) * 32 + lane;
            aH[t] = __ldg(&g_Xfrag[base]);
            aL[t] = __ldg(&g_Xfrag[base + 32]);
        }
        const uint2* bp = wf + (size_t)(k16 * 16) * 32;
        #pragma unroll
        for (int nt = 0; nt < 8; nt++) {
            uint2 b = __ldg(bp + nt * 32);
            mma_f16(acc[0][nt], &aH[0].x, b);
            mma_f16(acc[1][nt], &aH[1].x, b);
            mma_f16(acc[0][nt], &aL[0].x, b);
            mma_f16(acc[1][nt], &aL[1].x, b);
        }
    }

    // epilogue: fp16 stores
    #pragma unroll
    for (int t = 0; t < 2; t++) {
        #pragma unroll
        for (int nt = 0; nt < 8; nt++) {
            int row0 = rowBase + warpM * 32 + t * 16 + (lane >> 2);
            int col  = h * 128 + warpN * 64 + nt * 8 + (lane & 3) * 2;
            if (row0 < M)
                *reinterpret_cast<__half2*>(g_Yh + (size_t)row0 * 256 + col) =
                    __floats2half2_rn(acc[t][nt][0], acc[t][nt][1]);
            int row1 = row0 + 8;
            if (row1 < M)
                *reinterpret_cast<__half2*>(g_Yh + (size_t)row1 * 256 + col) =
                    __floats2half2_rn(acc[t][nt][2], acc[t][nt][3]);
        }
    }
}

// ---------------------------------------------------------------------------
// CSR build
// ---------------------------------------------------------------------------
__global__ void zero_cnt_kernel(int M) {
    int i = blockIdx.x * blockDim.x + threadIdx.x;
    if (i < M) g_cnt[i] = 0;
}

__global__ void hist_kernel(const int* __restrict__ erow, int E) {
    int i = blockIdx.x * blockDim.x + threadIdx.x;
    if (i < E) atomicAdd(&g_cnt[erow[i]], 1);
}

__global__ __launch_bounds__(SCAN_B)
void scan1_kernel(int M) {
    __shared__ int sh[SCAN_B];
    int tid = threadIdx.x;
    int i = blockIdx.x * SCAN_B + tid;
    int v = (i < M) ? g_cnt[i] : 0;
    sh[tid] = v;
    __syncthreads();
    #pragma unroll
    for (int d = 1; d < SCAN_B; d <<= 1) {
        int t = (tid >= d) ? sh[tid - d] : 0;
        __syncthreads();
        sh[tid] += t;
        __syncthreads();
    }
    if (i < M) g_off[i] = sh[tid] - v;
    if (tid == SCAN_B - 1) g_part[blockIdx.x] = sh[tid];
}

__global__ __launch_bounds__(256)
void scan3_kernel(int M, int E, int nb) {
    __shared__ int sh[MAX_SCAN_BLOCKS];
    int tid = threadIdx.x;
    if (tid < MAX_SCAN_BLOCKS) {
        int v = (tid < nb) ? g_part[tid] : 0;
        sh[tid] = v;
    }
    __syncthreads();
    if (tid < MAX_SCAN_BLOCKS) {
        #pragma unroll
        for (int d = 1; d < MAX_SCAN_BLOCKS; d <<= 1) {
            int t = (tid >= d) ? sh[tid - d] : 0;
            __syncthreads();
            sh[tid] += t;
            __syncthreads();
        }
    } else {
        #pragma unroll
        for (int d = 1; d < MAX_SCAN_BLOCKS; d <<= 1) {
            __syncthreads();
            __syncthreads();
        }
    }
    int i = blockIdx.x * blockDim.x + tid;
    if (i < M) {
        int b = i >> 10;
        int pre = (b == 0) ? 0 : sh[b - 1];
        int o = g_off[i] + pre;
        g_off[i] = o;
        g_cur[i] = o;
    }
    if (i == 0) g_off[M] = E;
}

__global__ void assign_kernel(const int* __restrict__ erow,
                              const int* __restrict__ ecol,
                              const float* __restrict__ eval, int E) {
    int i = blockIdx.x * blockDim.x + threadIdx.x;
    if (i < E) {
        int r = erow[i];
        int p = atomicAdd(&g_cur[r], 1);
        g_cv[p] = make_int2(ecol[i], __float_as_int(eval[i]));
    }
}

// ---------------------------------------------------------------------------
// SpMM over CSR: one warp per row; fp16 Y gather (one LDG.128 = 8 halves per
// lane per edge), fp32 register accumulation, bias fused.
// ---------------------------------------------------------------------------
__device__ __forceinline__ void acc_edge(float* a, uint4 y, float v) {
    float2 f;
    f = __half22float2(*reinterpret_cast<__half2*>(&y.x));
    a[0] += v * f.x; a[1] += v * f.y;
    f = __half22float2(*reinterpret_cast<__half2*>(&y.y));
    a[2] += v * f.x; a[3] += v * f.y;
    f = __half22float2(*reinterpret_cast<__half2*>(&y.z));
    a[4] += v * f.x; a[5] += v * f.y;
    f = __half22float2(*reinterpret_cast<__half2*>(&y.w));
    a[6] += v * f.x; a[7] += v * f.y;
}

__global__ __launch_bounds__(256)
void spmm_csr_kernel(const float* __restrict__ bias,
                     float* __restrict__ out, int M) {
    int warp = (blockIdx.x * blockDim.x + threadIdx.x) >> 5;
    int lane = threadIdx.x & 31;
    if (warp >= M) return;

    int start = g_off[warp];
    int end   = g_off[warp + 1];

    float a[8];
    {
        float4 b0 = reinterpret_cast<const float4*>(bias)[lane * 2 + 0];
        float4 b1 = reinterpret_cast<const float4*>(bias)[lane * 2 + 1];
        a[0] = b0.x; a[1] = b0.y; a[2] = b0.z; a[3] = b0.w;
        a[4] = b1.x; a[5] = b1.y; a[6] = b1.z; a[7] = b1.w;
    }

    for (int base = start; base < end; base += 32) {
        int idx = base + lane;
        int2 cvl = make_int2(0, 0);
        if (idx < end) cvl = g_cv[idx];
        int n = min(32, end - base);

        int j = 0;
        for (; j + 2 <= n; j += 2) {
            int   c0 = __shfl_sync(0xffffffffu, cvl.x, j);
            float v0 = __int_as_float(__shfl_sync(0xffffffffu, cvl.y, j));
            int   c1 = __shfl_sync(0xffffffffu, cvl.x, j + 1);
            float v1 = __int_as_float(__shfl_sync(0xffffffffu, cvl.y, j + 1));
            uint4 y0 = __ldg(reinterpret_cast<const uint4*>(
                g_Yh + (size_t)c0 * DIM) + lane);
            uint4 y1 = __ldg(reinterpret_cast<const uint4*>(
                g_Yh + (size_t)c1 * DIM) + lane);
            acc_edge(a, y0, v0);
            acc_edge(a, y1, v1);
        }
        if (j < n) {
            int   c0 = __shfl_sync(0xffffffffu, cvl.x, j);
            float v0 = __int_as_float(__shfl_sync(0xffffffffu, cvl.y, j));
            uint4 y0 = __ldg(reinterpret_cast<const uint4*>(
                g_Yh + (size_t)c0 * DIM) + lane);
            acc_edge(a, y0, v0);
        }
    }

    float4* o = reinterpret_cast<float4*>(out + (size_t)warp * DIM) + lane * 2;
    o[0] = make_float4(a[0], a[1], a[2], a[3]);
    o[1] = make_float4(a[4], a[5], a[6], a[7]);
}

// ---------------------------------------------------------------------------
// Launch: single side stream for CSR (R8-proven clean topology).
// ---------------------------------------------------------------------------
extern "C" void kernel_launch(void* const* d_in, const int* in_sizes, int n_in,
                              void* d_out, int out_size) {
    const float* X    = (const float*)d_in[0];
    const int*   erow = (const int*)  d_in[1];
    const int*   ecol = (const int*)  d_in[2];
    const float* eval = (const float*)d_in[3];
    const float* W    = (const float*)d_in[4];
    const float* bias = (const float*)d_in[5];
    float* out = (float*)d_out;

    int M = in_sizes[0] / DIM;   // 100000
    int E = in_sizes[1];         // 1600000
    int nScanBlocks = (M + SCAN_B - 1) / SCAN_B;
    int nTiles = (M + 127) / 128;

    cudaStream_t s2;
    cudaEvent_t ev0, evCsr;
    cudaStreamCreateWithFlags(&s2, cudaStreamNonBlocking);
    cudaEventCreateWithFlags(&ev0, cudaEventDisableTiming);
    cudaEventCreateWithFlags(&evCsr, cudaEventDisableTiming);

    // fork s2 off origin
    cudaEventRecord(ev0, 0);
    cudaStreamWaitEvent(s2, ev0, 0);

    // launch order (ncu profiles launch #4 = gemm):
    wprep_kernel<<<16384 / 256, 256>>>(W);                              // #1
    xprep_kernel<<<(MAX_TILES * 16 * 32) / 256, 256>>>(X, M);           // #2
    zero_cnt_kernel<<<(M + 255) / 256, 256, 0, s2>>>(M);                // #3
    gemm_tc_kernel<<<dim3(nTiles, 2), 256>>>(M);                        // #4
    hist_kernel<<<(E + 255) / 256, 256, 0, s2>>>(erow, E);              // #5
    scan1_kernel<<<nScanBlocks, SCAN_B, 0, s2>>>(M);                    // #6
    scan3_kernel<<<(M + 255) / 256, 256, 0, s2>>>(M, E, nScanBlocks);   // #7
    assign_kernel<<<(E + 255) / 256, 256, 0, s2>>>(erow, ecol, eval, E);// #8

    // join
    cudaEventRecord(evCsr, s2);
    cudaStreamWaitEvent(0, evCsr, 0);

    // out[r] = bias + sum_e v * Y[c]
    int rows_per_block = 256 / 32;
    spmm_csr_kernel<<<(M + rows_per_block - 1) / rows_per_block, 256>>>(bias, out, M); // #9
}

// round 11
// speedup vs baseline: 1.6391x; 1.0801x over previous
#include <cuda_runtime.h>
#include <cuda_bf16.h>
#include <cuda_fp16.h>
#include <cstdint>

#define DIM 256
#define MAX_TILES 6256                    // 782 blocks * 8 row16-tiles
#define MAX_NODES (MAX_TILES * 16)        // 100096
#define MAX_EDGES 1600000
#define SCAN_B 1024
#define MAX_SCAN_BLOCKS 128

// Scratch (static device globals — no allocation allowed)
static __device__ __half g_Yh[(size_t)MAX_NODES * DIM];       // Y = X @ W (fp16)
static __device__ int    g_cnt[MAX_NODES];
static __device__ int    g_off[MAX_NODES + 1];
static __device__ int    g_cur[MAX_NODES];
static __device__ int    g_part[MAX_SCAN_BLOCKS];
static __device__ int2   g_cv[MAX_EDGES];
// A fragments of X, fp16 hi/lo split: [tile][k16][hl][lane] uint4  (102 MB)
static __device__ uint4  g_Xfrag[(size_t)MAX_TILES * 16 * 2 * 32];
// B fragments of W (fp16): [h][k16][n8][lane] uint2  (128 KB)
static __device__ uint2  g_Wfrag[2 * 16 * 16 * 32];

// ---------------------------------------------------------------------------
// helpers
// ---------------------------------------------------------------------------
__device__ __forceinline__ void mma_f16(float* d, const uint32_t* a, uint2 b) {
    asm volatile(
        "mma.sync.aligned.m16n8k16.row.col.f32.f16.f16.f32 "
        "{%0,%1,%2,%3}, {%4,%5,%6,%7}, {%8,%9}, {%0,%1,%2,%3};"
        : "+f"(d[0]), "+f"(d[1]), "+f"(d[2]), "+f"(d[3])
        : "r"(a[0]), "r"(a[1]), "r"(a[2]), "r"(a[3]), "r"(b.x), "r"(b.y));
}
__device__ __forceinline__ uint32_t pack_h2(float a, float b) {
    __half2 h = __floats2half2_rn(a, b);
    return *reinterpret_cast<uint32_t*>(&h);
}
__device__ __forceinline__ uint32_t pack_h2res(float2 v, uint32_t hi) {
    __half2 hh = *reinterpret_cast<__half2*>(&hi);
    float2 f = __half22float2(hh);
    return pack_h2(v.x - f.x, v.y - f.y);
}

// ---------------------------------------------------------------------------
// W prep: fp16 per-lane mma B-fragment bake.
// ---------------------------------------------------------------------------
__global__ void wprep_kernel(const float* __restrict__ W) {
    int i = blockIdx.x * blockDim.x + threadIdx.x;
    if (i >= 16384) return;
    int lane = i & 31;
    int n8   = (i >> 5) & 15;
    int k16  = (i >> 9) & 15;
    int h    = (i >> 13) & 1;
    int n  = h * 128 + n8 * 8 + (lane >> 2);
    int kb = k16 * 16 + (lane & 3) * 2;
    uint2 o;
    o.x = pack_h2(W[(size_t)kb * 256 + n],       W[(size_t)(kb + 1) * 256 + n]);
    o.y = pack_h2(W[(size_t)(kb + 8) * 256 + n], W[(size_t)(kb + 9) * 256 + n]);
    g_Wfrag[i] = o;
}

// ---------------------------------------------------------------------------
// X prep: fp16 hi/lo split, baked into per-lane mma A-fragments.
// ---------------------------------------------------------------------------
__global__ __launch_bounds__(256)
void xprep_kernel(const float* __restrict__ X, int M) {
    int i = blockIdx.x * blockDim.x + threadIdx.x;   // MAX_TILES*16*32 threads
    int lane = i & 31;
    int k16  = (i >> 5) & 15;
    int tile = i >> 9;
    if (tile >= MAX_TILES) return;

    int r0 = tile * 16 + (lane >> 2);
    int r1 = r0 + 8;
    int col = k16 * 16 + (lane & 3) * 2;
    float2 z = make_float2(0.f, 0.f);
    float2 f00 = (r0 < M) ? __ldg((const float2*)(X + (size_t)r0 * 256 + col))     : z;
    float2 f01 = (r0 < M) ? __ldg((const float2*)(X + (size_t)r0 * 256 + col + 8)) : z;
    float2 f10 = (r1 < M) ? __ldg((const float2*)(X + (size_t)r1 * 256 + col))     : z;
    float2 f11 = (r1 < M) ? __ldg((const float2*)(X + (size_t)r1 * 256 + col + 8)) : z;

    uint4 aH, aL;
    aH.x = pack_h2(f00.x, f00.y);
    aH.y = pack_h2(f10.x, f10.y);
    aH.z = pack_h2(f01.x, f01.y);
    aH.w = pack_h2(f11.x, f11.y);
    aL.x = pack_h2res(f00, aH.x);
    aL.y = pack_h2res(f10, aH.y);
    aL.z = pack_h2res(f01, aH.z);
    aL.w = pack_h2res(f11, aH.w);

    size_t base = ((size_t)(tile * 16 + k16) * 2) * 32 + lane;
    g_Xfrag[base]      = aH;
    g_Xfrag[base + 32] = aL;
}

// ---------------------------------------------------------------------------
// HMMA GEMM (fp16 2-product split), smem-free, pre-baked fragments.
// CTA = 128 rows x FULL N=256 via internal h-loop (A reused from L1/L2 on
// the second half -> DRAM A-traffic halved). 8 warps: 4M x 2N per half.
// ---------------------------------------------------------------------------
__global__ __launch_bounds__(256, 2)
void gemm_tc_kernel(int M) {
    const int lane  = threadIdx.x & 31;
    const int wid   = threadIdx.x >> 5;
    const int warpM = wid & 3;
    const int warpN = wid >> 2;
    const int rowBase = blockIdx.x * 128;
    const int tile0 = blockIdx.x * 8 + warpM * 2;

    #pragma unroll
    for (int h = 0; h < 2; h++) {
        float acc[2][8][4];
        #pragma unroll
        for (int t = 0; t < 2; t++)
            #pragma unroll
            for (int nt = 0; nt < 8; nt++)
                #pragma unroll
                for (int e = 0; e < 4; e++)
                    acc[t][nt][e] = 0.f;

        const uint2* __restrict__ wf = g_Wfrag
            + (((size_t)h * 16) * 16 + (size_t)warpN * 8) * 32 + lane;

        #pragma unroll 2
        for (int k16 = 0; k16 < 16; k16++) {
            uint4 aH[2], aL[2];
            #pragma unroll
            for (int t = 0; t < 2; t++) {
                size_t base = ((size_t)((tile0 + t) * 16 + k16) * 2) * 32 + lane;
                aH[t] = __ldg(&g_Xfrag[base]);
                aL[t] = __ldg(&g_Xfrag[base + 32]);
            }
            const uint2* bp = wf + (size_t)(k16 * 16) * 32;
            #pragma unroll
            for (int nt = 0; nt < 8; nt++) {
                uint2 b = __ldg(bp + nt * 32);
                mma_f16(acc[0][nt], &aH[0].x, b);
                mma_f16(acc[1][nt], &aH[1].x, b);
                mma_f16(acc[0][nt], &aL[0].x, b);
                mma_f16(acc[1][nt], &aL[1].x, b);
            }
        }

        // epilogue: fp16 stores for this half
        #pragma unroll
        for (int t = 0; t < 2; t++) {
            #pragma unroll
            for (int nt = 0; nt < 8; nt++) {
                int row0 = rowBase + warpM * 32 + t * 16 + (lane >> 2);
                int col  = h * 128 + warpN * 64 + nt * 8 + (lane & 3) * 2;
                if (row0 < M)
                    *reinterpret_cast<__half2*>(g_Yh + (size_t)row0 * 256 + col) =
                        __floats2half2_rn(acc[t][nt][0], acc[t][nt][1]);
                int row1 = row0 + 8;
                if (row1 < M)
                    *reinterpret_cast<__half2*>(g_Yh + (size_t)row1 * 256 + col) =
                        __floats2half2_rn(acc[t][nt][2], acc[t][nt][3]);
            }
        }
    }
}

// ---------------------------------------------------------------------------
// CSR build
// ---------------------------------------------------------------------------
__global__ void zero_cnt_kernel(int M) {
    int i = blockIdx.x * blockDim.x + threadIdx.x;
    if (i < M) g_cnt[i] = 0;
}

__global__ void hist_kernel(const int* __restrict__ erow, int E) {
    int i = blockIdx.x * blockDim.x + threadIdx.x;
    if (i < E) atomicAdd(&g_cnt[erow[i]], 1);
}

__global__ __launch_bounds__(SCAN_B)
void scan1_kernel(int M) {
    __shared__ int sh[SCAN_B];
    int tid = threadIdx.x;
    int i = blockIdx.x * SCAN_B + tid;
    int v = (i < M) ? g_cnt[i] : 0;
    sh[tid] = v;
    __syncthreads();
    #pragma unroll
    for (int d = 1; d < SCAN_B; d <<= 1) {
        int t = (tid >= d) ? sh[tid - d] : 0;
        __syncthreads();
        sh[tid] += t;
        __syncthreads();
    }
    if (i < M) g_off[i] = sh[tid] - v;
    if (tid == SCAN_B - 1) g_part[blockIdx.x] = sh[tid];
}

__global__ __launch_bounds__(256)
void scan3_kernel(int M, int E, int nb) {
    __shared__ int sh[MAX_SCAN_BLOCKS];
    int tid = threadIdx.x;
    if (tid < MAX_SCAN_BLOCKS) {
        int v = (tid < nb) ? g_part[tid] : 0;
        sh[tid] = v;
    }
    __syncthreads();
    if (tid < MAX_SCAN_BLOCKS) {
        #pragma unroll
        for (int d = 1; d < MAX_SCAN_BLOCKS; d <<= 1) {
            int t = (tid >= d) ? sh[tid - d] : 0;
            __syncthreads();
            sh[tid] += t;
            __syncthreads();
        }
    } else {
        #pragma unroll
        for (int d = 1; d < MAX_SCAN_BLOCKS; d <<= 1) {
            __syncthreads();
            __syncthreads();
        }
    }
    int i = blockIdx.x * blockDim.x + tid;
    if (i < M) {
        int b = i >> 10;
        int pre = (b == 0) ? 0 : sh[b - 1];
        int o = g_off[i] + pre;
        g_off[i] = o;
        g_cur[i] = o;
    }
    if (i == 0) g_off[M] = E;
}

__global__ void assign_kernel(const int* __restrict__ erow,
                              const int* __restrict__ ecol,
                              const float* __restrict__ eval, int E) {
    int i = blockIdx.x * blockDim.x + threadIdx.x;
    if (i < E) {
        int r = erow[i];
        int p = atomicAdd(&g_cur[r], 1);
        g_cv[p] = make_int2(ecol[i], __float_as_int(eval[i]));
    }
}

// ---------------------------------------------------------------------------
// SpMM over CSR: one warp per row; fp16 Y gather (one LDG.128 = 8 halves per
// lane per edge), fp32 register accumulation, bias fused.
// ---------------------------------------------------------------------------
__device__ __forceinline__ void acc_edge(float* a, uint4 y, float v) {
    float2 f;
    f = __half22float2(*reinterpret_cast<__half2*>(&y.x));
    a[0] += v * f.x; a[1] += v * f.y;
    f = __half22float2(*reinterpret_cast<__half2*>(&y.y));
    a[2] += v * f.x; a[3] += v * f.y;
    f = __half22float2(*reinterpret_cast<__half2*>(&y.z));
    a[4] += v * f.x; a[5] += v * f.y;
    f = __half22float2(*reinterpret_cast<__half2*>(&y.w));
    a[6] += v * f.x; a[7] += v * f.y;
}

__global__ __launch_bounds__(256)
void spmm_csr_kernel(const float* __restrict__ bias,
                     float* __restrict__ out, int M) {
    int warp = (blockIdx.x * blockDim.x + threadIdx.x) >> 5;
    int lane = threadIdx.x & 31;
    if (warp >= M) return;

    int start = g_off[warp];
    int end   = g_off[warp + 1];

    float a[8];
    {
        float4 b0 = reinterpret_cast<const float4*>(bias)[lane * 2 + 0];
        float4 b1 = reinterpret_cast<const float4*>(bias)[lane * 2 + 1];
        a[0] = b0.x; a[1] = b0.y; a[2] = b0.z; a[3] = b0.w;
        a[4] = b1.x; a[5] = b1.y; a[6] = b1.z; a[7] = b1.w;
    }

    for (int base = start; base < end; base += 32) {
        int idx = base + lane;
        int2 cvl = make_int2(0, 0);
        if (idx < end) cvl = g_cv[idx];
        int n = min(32, end - base);

        int j = 0;
        for (; j + 2 <= n; j += 2) {
            int   c0 = __shfl_sync(0xffffffffu, cvl.x, j);
            float v0 = __int_as_float(__shfl_sync(0xffffffffu, cvl.y, j));
            int   c1 = __shfl_sync(0xffffffffu, cvl.x, j + 1);
            float v1 = __int_as_float(__shfl_sync(0xffffffffu, cvl.y, j + 1));
            uint4 y0 = __ldg(reinterpret_cast<const uint4*>(
                g_Yh + (size_t)c0 * DIM) + lane);
            uint4 y1 = __ldg(reinterpret_cast<const uint4*>(
                g_Yh + (size_t)c1 * DIM) + lane);
            acc_edge(a, y0, v0);
            acc_edge(a, y1, v1);
        }
        if (j < n) {
            int   c0 = __shfl_sync(0xffffffffu, cvl.x, j);
            float v0 = __int_as_float(__shfl_sync(0xffffffffu, cvl.y, j));
            uint4 y0 = __ldg(reinterpret_cast<const uint4*>(
                g_Yh + (size_t)c0 * DIM) + lane);
            acc_edge(a, y0, v0);
        }
    }

    float4* o = reinterpret_cast<float4*>(out + (size_t)warp * DIM) + lane * 2;
    o[0] = make_float4(a[0], a[1], a[2], a[3]);
    o[1] = make_float4(a[4], a[5], a[6], a[7]);
}

// ---------------------------------------------------------------------------
// Launch: single side stream for CSR (R8-proven clean topology).
// ---------------------------------------------------------------------------
extern "C" void kernel_launch(void* const* d_in, const int* in_sizes, int n_in,
                              void* d_out, int out_size) {
    const float* X    = (const float*)d_in[0];
    const int*   erow = (const int*)  d_in[1];
    const int*   ecol = (const int*)  d_in[2];
    const float* eval = (const float*)d_in[3];
    const float* W    = (const float*)d_in[4];
    const float* bias = (const float*)d_in[5];
    float* out = (float*)d_out;

    int M = in_sizes[0] / DIM;   // 100000
    int E = in_sizes[1];         // 1600000
    int nScanBlocks = (M + SCAN_B - 1) / SCAN_B;
    int nTiles = (M + 127) / 128;

    cudaStream_t s2;
    cudaEvent_t ev0, evCsr;
    cudaStreamCreateWithFlags(&s2, cudaStreamNonBlocking);
    cudaEventCreateWithFlags(&ev0, cudaEventDisableTiming);
    cudaEventCreateWithFlags(&evCsr, cudaEventDisableTiming);

    // fork s2 off origin
    cudaEventRecord(ev0, 0);
    cudaStreamWaitEvent(s2, ev0, 0);

    // launch order (ncu profiles launch #4 = gemm):
    wprep_kernel<<<16384 / 256, 256>>>(W);                              // #1
    xprep_kernel<<<(MAX_TILES * 16 * 32) / 256, 256>>>(X, M);           // #2
    zero_cnt_kernel<<<(M + 255) / 256, 256, 0, s2>>>(M);                // #3
    gemm_tc_kernel<<<nTiles, 256>>>(M);                                 // #4
    hist_kernel<<<(E + 255) / 256, 256, 0, s2>>>(erow, E);              // #5
    scan1_kernel<<<nScanBlocks, SCAN_B, 0, s2>>>(M);                    // #6
    scan3_kernel<<<(M + 255) / 256, 256, 0, s2>>>(M, E, nScanBlocks);   // #7
    assign_kernel<<<(E + 255) / 256, 256, 0, s2>>>(erow, ecol, eval, E);// #8

    // join
    cudaEventRecord(evCsr, s2);
    cudaStreamWaitEvent(0, evCsr, 0);

    // out[r] = bias + sum_e v * Y[c]
    int rows_per_block = 256 / 32;
    spmm_csr_kernel<<<(M + rows_per_block - 1) / rows_per_block, 256>>>(bias, out, M); // #9
}

// round 12
// speedup vs baseline: 1.8333x; 1.1185x over previous
#include <cuda_runtime.h>
#include <cuda_bf16.h>
#include <cuda_fp16.h>
#include <cstdint>

#define DIM 256
#define MAX_TILES 6256                    // 782 blocks * 8 row16-tiles
#define MAX_NODES (MAX_TILES * 16)        // 100096
#define MAX_EDGES 1600000
#define SCAN_B 1024
#define MAX_SCAN_BLOCKS 128

// Scratch (static device globals — no allocation allowed)
static __device__ __half g_Yh[(size_t)MAX_NODES * DIM];       // Y = X @ W (fp16)
static __device__ int    g_cnt[MAX_NODES];
static __device__ int    g_off[MAX_NODES + 1];
static __device__ int    g_cur[MAX_NODES];
static __device__ int    g_part[MAX_SCAN_BLOCKS];
static __device__ int2   g_cv[MAX_EDGES];
// A fragments of X (fp16): [tile][k16][lane] uint4   (51 MB)
static __device__ uint4  g_Xfrag[(size_t)MAX_TILES * 16 * 32];
// B fragments of W (fp16): [h][k16][n8][lane] uint2  (128 KB)
static __device__ uint2  g_Wfrag[2 * 16 * 16 * 32];

// ---------------------------------------------------------------------------
// helpers
// ---------------------------------------------------------------------------
__device__ __forceinline__ void mma_f16(float* d, const uint32_t* a, uint2 b) {
    asm volatile(
        "mma.sync.aligned.m16n8k16.row.col.f32.f16.f16.f32 "
        "{%0,%1,%2,%3}, {%4,%5,%6,%7}, {%8,%9}, {%0,%1,%2,%3};"
        : "+f"(d[0]), "+f"(d[1]), "+f"(d[2]), "+f"(d[3])
        : "r"(a[0]), "r"(a[1]), "r"(a[2]), "r"(a[3]), "r"(b.x), "r"(b.y));
}
__device__ __forceinline__ uint32_t pack_h2(float a, float b) {
    __half2 h = __floats2half2_rn(a, b);
    return *reinterpret_cast<uint32_t*>(&h);
}

// ---------------------------------------------------------------------------
// W prep: fp16 per-lane mma B-fragment bake.
// ---------------------------------------------------------------------------
__global__ void wprep_kernel(const float* __restrict__ W) {
    int i = blockIdx.x * blockDim.x + threadIdx.x;
    if (i >= 16384) return;
    int lane = i & 31;
    int n8   = (i >> 5) & 15;
    int k16  = (i >> 9) & 15;
    int h    = (i >> 13) & 1;
    int n  = h * 128 + n8 * 8 + (lane >> 2);
    int kb = k16 * 16 + (lane & 3) * 2;
    uint2 o;
    o.x = pack_h2(W[(size_t)kb * 256 + n],       W[(size_t)(kb + 1) * 256 + n]);
    o.y = pack_h2(W[(size_t)(kb + 8) * 256 + n], W[(size_t)(kb + 9) * 256 + n]);
    g_Wfrag[i] = o;
}

// ---------------------------------------------------------------------------
// X prep: fp16 conversion baked into per-lane mma A-fragments.
// ---------------------------------------------------------------------------
__global__ __launch_bounds__(256)
void xprep_kernel(const float* __restrict__ X, int M) {
    int i = blockIdx.x * blockDim.x + threadIdx.x;   // MAX_TILES*16*32 threads
    int lane = i & 31;
    int k16  = (i >> 5) & 15;
    int tile = i >> 9;
    if (tile >= MAX_TILES) return;

    int r0 = tile * 16 + (lane >> 2);
    int r1 = r0 + 8;
    int col = k16 * 16 + (lane & 3) * 2;
    float2 z = make_float2(0.f, 0.f);
    float2 f00 = (r0 < M) ? __ldg((const float2*)(X + (size_t)r0 * 256 + col))     : z;
    float2 f01 = (r0 < M) ? __ldg((const float2*)(X + (size_t)r0 * 256 + col + 8)) : z;
    float2 f10 = (r1 < M) ? __ldg((const float2*)(X + (size_t)r1 * 256 + col))     : z;
    float2 f11 = (r1 < M) ? __ldg((const float2*)(X + (size_t)r1 * 256 + col + 8)) : z;

    uint4 aH;
    aH.x = pack_h2(f00.x, f00.y);
    aH.y = pack_h2(f10.x, f10.y);
    aH.z = pack_h2(f01.x, f01.y);
    aH.w = pack_h2(f11.x, f11.y);

    g_Xfrag[(size_t)(tile * 16 + k16) * 32 + lane] = aH;
}

// ---------------------------------------------------------------------------
// HMMA GEMM (fp16), smem-free, pre-baked fragments.
// CTA = 128 rows x FULL N=256 via internal h-loop (A reused from L1/L2 on
// the second half). 8 warps: 4M x 2N per half. 256 MMAs per warp total.
// ---------------------------------------------------------------------------
__global__ __launch_bounds__(256, 2)
void gemm_tc_kernel(int M) {
    const int lane  = threadIdx.x & 31;
    const int wid   = threadIdx.x >> 5;
    const int warpM = wid & 3;
    const int warpN = wid >> 2;
    const int rowBase = blockIdx.x * 128;
    const int tile0 = blockIdx.x * 8 + warpM * 2;

    #pragma unroll
    for (int h = 0; h < 2; h++) {
        float acc[2][8][4];
        #pragma unroll
        for (int t = 0; t < 2; t++)
            #pragma unroll
            for (int nt = 0; nt < 8; nt++)
                #pragma unroll
                for (int e = 0; e < 4; e++)
                    acc[t][nt][e] = 0.f;

        const uint2* __restrict__ wf = g_Wfrag
            + (((size_t)h * 16) * 16 + (size_t)warpN * 8) * 32 + lane;

        #pragma unroll 4
        for (int k16 = 0; k16 < 16; k16++) {
            uint4 aH[2];
            #pragma unroll
            for (int t = 0; t < 2; t++)
                aH[t] = __ldg(&g_Xfrag[(size_t)((tile0 + t) * 16 + k16) * 32 + lane]);
            const uint2* bp = wf + (size_t)(k16 * 16) * 32;
            #pragma unroll
            for (int nt = 0; nt < 8; nt++) {
                uint2 b = __ldg(bp + nt * 32);
                mma_f16(acc[0][nt], &aH[0].x, b);
                mma_f16(acc[1][nt], &aH[1].x, b);
            }
        }

        // epilogue: fp16 stores for this half
        #pragma unroll
        for (int t = 0; t < 2; t++) {
            #pragma unroll
            for (int nt = 0; nt < 8; nt++) {
                int row0 = rowBase + warpM * 32 + t * 16 + (lane >> 2);
                int col  = h * 128 + warpN * 64 + nt * 8 + (lane & 3) * 2;
                if (row0 < M)
                    *reinterpret_cast<__half2*>(g_Yh + (size_t)row0 * 256 + col) =
                        __floats2half2_rn(acc[t][nt][0], acc[t][nt][1]);
                int row1 = row0 + 8;
                if (row1 < M)
                    *reinterpret_cast<__half2*>(g_Yh + (size_t)row1 * 256 + col) =
                        __floats2half2_rn(acc[t][nt][2], acc[t][nt][3]);
            }
        }
    }
}

// ---------------------------------------------------------------------------
// CSR build
// ---------------------------------------------------------------------------
__global__ void zero_cnt_kernel(int M) {
    int i = blockIdx.x * blockDim.x + threadIdx.x;
    if (i < M) g_cnt[i] = 0;
}

__global__ void hist_kernel(const int* __restrict__ erow, int E) {
    int i = blockIdx.x * blockDim.x + threadIdx.x;
    if (i < E) atomicAdd(&g_cnt[erow[i]], 1);
}

__global__ __launch_bounds__(SCAN_B)
void scan1_kernel(int M) {
    __shared__ int sh[SCAN_B];
    int tid = threadIdx.x;
    int i = blockIdx.x * SCAN_B + tid;
    int v = (i < M) ? g_cnt[i] : 0;
    sh[tid] = v;
    __syncthreads();
    #pragma unroll
    for (int d = 1; d < SCAN_B; d <<= 1) {
        int t = (tid >= d) ? sh[tid - d] : 0;
        __syncthreads();
        sh[tid] += t;
        __syncthreads();
    }
    if (i < M) g_off[i] = sh[tid] - v;
    if (tid == SCAN_B - 1) g_part[blockIdx.x] = sh[tid];
}

__global__ __launch_bounds__(256)
void scan3_kernel(int M, int E, int nb) {
    __shared__ int sh[MAX_SCAN_BLOCKS];
    int tid = threadIdx.x;
    if (tid < MAX_SCAN_BLOCKS) {
        int v = (tid < nb) ? g_part[tid] : 0;
        sh[tid] = v;
    }
    __syncthreads();
    if (tid < MAX_SCAN_BLOCKS) {
        #pragma unroll
        for (int d = 1; d < MAX_SCAN_BLOCKS; d <<= 1) {
            int t = (tid >= d) ? sh[tid - d] : 0;
            __syncthreads();
            sh[tid] += t;
            __syncthreads();
        }
    } else {
        #pragma unroll
        for (int d = 1; d < MAX_SCAN_BLOCKS; d <<= 1) {
            __syncthreads();
            __syncthreads();
        }
    }
    int i = blockIdx.x * blockDim.x + tid;
    if (i < M) {
        int b = i >> 10;
        int pre = (b == 0) ? 0 : sh[b - 1];
        int o = g_off[i] + pre;
        g_off[i] = o;
        g_cur[i] = o;
    }
    if (i == 0) g_off[M] = E;
}

__global__ void assign_kernel(const int* __restrict__ erow,
                              const int* __restrict__ ecol,
                              const float* __restrict__ eval, int E) {
    int i = blockIdx.x * blockDim.x + threadIdx.x;
    if (i < E) {
        int r = erow[i];
        int p = atomicAdd(&g_cur[r], 1);
        g_cv[p] = make_int2(ecol[i], __float_as_int(eval[i]));
    }
}

// ---------------------------------------------------------------------------
// SpMM over CSR: one warp per row; fp16 Y gather (one LDG.128 = 8 halves per
// lane per edge), fp32 register accumulation, bias fused.
// ---------------------------------------------------------------------------
__device__ __forceinline__ void acc_edge(float* a, uint4 y, float v) {
    float2 f;
    f = __half22float2(*reinterpret_cast<__half2*>(&y.x));
    a[0] += v * f.x; a[1] += v * f.y;
    f = __half22float2(*reinterpret_cast<__half2*>(&y.y));
    a[2] += v * f.x; a[3] += v * f.y;
    f = __half22float2(*reinterpret_cast<__half2*>(&y.z));
    a[4] += v * f.x; a[5] += v * f.y;
    f = __half22float2(*reinterpret_cast<__half2*>(&y.w));
    a[6] += v * f.x; a[7] += v * f.y;
}

__global__ __launch_bounds__(256)
void spmm_csr_kernel(const float* __restrict__ bias,
                     float* __restrict__ out, int M) {
    int warp = (blockIdx.x * blockDim.x + threadIdx.x) >> 5;
    int lane = threadIdx.x & 31;
    if (warp >= M) return;

    int start = g_off[warp];
    int end   = g_off[warp + 1];

    float a[8];
    {
        float4 b0 = reinterpret_cast<const float4*>(bias)[lane * 2 + 0];
        float4 b1 = reinterpret_cast<const float4*>(bias)[lane * 2 + 1];
        a[0] = b0.x; a[1] = b0.y; a[2] = b0.z; a[3] = b0.w;
        a[4] = b1.x; a[5] = b1.y; a[6] = b1.z; a[7] = b1.w;
    }

    for (int base = start; base < end; base += 32) {
        int idx = base + lane;
        int2 cvl = make_int2(0, 0);
        if (idx < end) cvl = g_cv[idx];
        int n = min(32, end - base);

        int j = 0;
        for (; j + 2 <= n; j += 2) {
            int   c0 = __shfl_sync(0xffffffffu, cvl.x, j);
            float v0 = __int_as_float(__shfl_sync(0xffffffffu, cvl.y, j));
            int   c1 = __shfl_sync(0xffffffffu, cvl.x, j + 1);
            float v1 = __int_as_float(__shfl_sync(0xffffffffu, cvl.y, j + 1));
            uint4 y0 = __ldg(reinterpret_cast<const uint4*>(
                g_Yh + (size_t)c0 * DIM) + lane);
            uint4 y1 = __ldg(reinterpret_cast<const uint4*>(
                g_Yh + (size_t)c1 * DIM) + lane);
            acc_edge(a, y0, v0);
            acc_edge(a, y1, v1);
        }
        if (j < n) {
            int   c0 = __shfl_sync(0xffffffffu, cvl.x, j);
            float v0 = __int_as_float(__shfl_sync(0xffffffffu, cvl.y, j));
            uint4 y0 = __ldg(reinterpret_cast<const uint4*>(
                g_Yh + (size_t)c0 * DIM) + lane);
            acc_edge(a, y0, v0);
        }
    }

    float4* o = reinterpret_cast<float4*>(out + (size_t)warp * DIM) + lane * 2;
    o[0] = make_float4(a[0], a[1], a[2], a[3]);
    o[1] = make_float4(a[4], a[5], a[6], a[7]);
}

// ---------------------------------------------------------------------------
// Launch: single side stream for CSR (clean topology).
// ---------------------------------------------------------------------------
extern "C" void kernel_launch(void* const* d_in, const int* in_sizes, int n_in,
                              void* d_out, int out_size) {
    const float* X    = (const float*)d_in[0];
    const int*   erow = (const int*)  d_in[1];
    const int*   ecol = (const int*)  d_in[2];
    const float* eval = (const float*)d_in[3];
    const float* W    = (const float*)d_in[4];
    const float* bias = (const float*)d_in[5];
    float* out = (float*)d_out;

    int M = in_sizes[0] / DIM;   // 100000
    int E = in_sizes[1];         // 1600000
    int nScanBlocks = (M + SCAN_B - 1) / SCAN_B;
    int nTiles = (M + 127) / 128;

    cudaStream_t s2;
    cudaEvent_t ev0, evCsr;
    cudaStreamCreateWithFlags(&s2, cudaStreamNonBlocking);
    cudaEventCreateWithFlags(&ev0, cudaEventDisableTiming);
    cudaEventCreateWithFlags(&evCsr, cudaEventDisableTiming);

    // fork s2 off origin
    cudaEventRecord(ev0, 0);
    cudaStreamWaitEvent(s2, ev0, 0);

    // launch order (ncu profiles launch #4 = gemm):
    wprep_kernel<<<16384 / 256, 256>>>(W);                              // #1
    xprep_kernel<<<(MAX_TILES * 16 * 32) / 256, 256>>>(X, M);           // #2
    zero_cnt_kernel<<<(M + 255) / 256, 256, 0, s2>>>(M);                // #3
    gemm_tc_kernel<<<nTiles, 256>>>(M);                                 // #4
    hist_kernel<<<(E + 255) / 256, 256, 0, s2>>>(erow, E);              // #5
    scan1_kernel<<<nScanBlocks, SCAN_B, 0, s2>>>(M);                    // #6
    scan3_kernel<<<(M + 255) / 256, 256, 0, s2>>>(M, E, nScanBlocks);   // #7
    assign_kernel<<<(E + 255) / 256, 256, 0, s2>>>(erow, ecol, eval, E);// #8

    // join
    cudaEventRecord(evCsr, s2);
    cudaStreamWaitEvent(0, evCsr, 0);

    // out[r] = bias + sum_e v * Y[c]
    int rows_per_block = 256 / 32;
    spmm_csr_kernel<<<(M + rows_per_block - 1) / rows_per_block, 256>>>(bias, out, M); // #9
}

// round 13
// speedup vs baseline: 1.8342x; 1.0005x over previous
#include <cuda_runtime.h>
#include <cuda_bf16.h>
#include <cuda_fp16.h>
#include <cstdint>

#define DIM 256
#define MAX_TILES 6256                    // 782 blocks * 8 row16-tiles
#define MAX_NODES (MAX_TILES * 16)        // 100096
#define MAX_EDGES 1600000
#define SCAN_B 1024
#define MAX_SCAN_BLOCKS 128

// Scratch (static device globals — no allocation allowed)
static __device__ __half g_Yh[(size_t)MAX_NODES * DIM];       // Y = X @ W (fp16)
static __device__ int    g_cnt[MAX_NODES];
static __device__ int    g_off[MAX_NODES + 1];
static __device__ int    g_cur[MAX_NODES];
static __device__ int    g_part[MAX_SCAN_BLOCKS];
static __device__ int2   g_cv[MAX_EDGES];
// A fragments of X (fp16): [tile][k16][lane] uint4   (51 MB)
static __device__ uint4  g_Xfrag[(size_t)MAX_TILES * 16 * 32];
// B fragments of W (fp16): [h][k16][n8][lane] uint2  (128 KB)
static __device__ uint2  g_Wfrag[2 * 16 * 16 * 32];

// ---------------------------------------------------------------------------
// helpers
// ---------------------------------------------------------------------------
__device__ __forceinline__ void mma_f16(float* d, const uint32_t* a, uint2 b) {
    asm volatile(
        "mma.sync.aligned.m16n8k16.row.col.f32.f16.f16.f32 "
        "{%0,%1,%2,%3}, {%4,%5,%6,%7}, {%8,%9}, {%0,%1,%2,%3};"
        : "+f"(d[0]), "+f"(d[1]), "+f"(d[2]), "+f"(d[3])
        : "r"(a[0]), "r"(a[1]), "r"(a[2]), "r"(a[3]), "r"(b.x), "r"(b.y));
}
__device__ __forceinline__ uint32_t pack_h2(float a, float b) {
    __half2 h = __floats2half2_rn(a, b);
    return *reinterpret_cast<uint32_t*>(&h);
}

// ---------------------------------------------------------------------------
// W prep: fp16 per-lane mma B-fragment bake.
// ---------------------------------------------------------------------------
__global__ void wprep_kernel(const float* __restrict__ W) {
    int i = blockIdx.x * blockDim.x + threadIdx.x;
    if (i >= 16384) return;
    int lane = i & 31;
    int n8   = (i >> 5) & 15;
    int k16  = (i >> 9) & 15;
    int h    = (i >> 13) & 1;
    int n  = h * 128 + n8 * 8 + (lane >> 2);
    int kb = k16 * 16 + (lane & 3) * 2;
    uint2 o;
    o.x = pack_h2(W[(size_t)kb * 256 + n],       W[(size_t)(kb + 1) * 256 + n]);
    o.y = pack_h2(W[(size_t)(kb + 8) * 256 + n], W[(size_t)(kb + 9) * 256 + n]);
    g_Wfrag[i] = o;
}

// ---------------------------------------------------------------------------
// X prep: fp16 conversion baked into per-lane mma A-fragments.
// ---------------------------------------------------------------------------
__global__ __launch_bounds__(256)
void xprep_kernel(const float* __restrict__ X, int M) {
    int i = blockIdx.x * blockDim.x + threadIdx.x;   // MAX_TILES*16*32 threads
    int lane = i & 31;
    int k16  = (i >> 5) & 15;
    int tile = i >> 9;
    if (tile >= MAX_TILES) return;

    int r0 = tile * 16 + (lane >> 2);
    int r1 = r0 + 8;
    int col = k16 * 16 + (lane & 3) * 2;
    float2 z = make_float2(0.f, 0.f);
    float2 f00 = (r0 < M) ? __ldg((const float2*)(X + (size_t)r0 * 256 + col))     : z;
    float2 f01 = (r0 < M) ? __ldg((const float2*)(X + (size_t)r0 * 256 + col + 8)) : z;
    float2 f10 = (r1 < M) ? __ldg((const float2*)(X + (size_t)r1 * 256 + col))     : z;
    float2 f11 = (r1 < M) ? __ldg((const float2*)(X + (size_t)r1 * 256 + col + 8)) : z;

    uint4 aH;
    aH.x = pack_h2(f00.x, f00.y);
    aH.y = pack_h2(f10.x, f10.y);
    aH.z = pack_h2(f01.x, f01.y);
    aH.w = pack_h2(f11.x, f11.y);

    g_Xfrag[(size_t)(tile * 16 + k16) * 32 + lane] = aH;
}

// ---------------------------------------------------------------------------
// HMMA GEMM (fp16), smem-free, pre-baked fragments.
// CTA = 128 rows x FULL N=256 via internal h-loop (A reused from L1/L2 on
// the second half). 8 warps: 4M x 2N per half. 256 MMAs per warp total.
// ---------------------------------------------------------------------------
__global__ __launch_bounds__(256, 2)
void gemm_tc_kernel(int M) {
    const int lane  = threadIdx.x & 31;
    const int wid   = threadIdx.x >> 5;
    const int warpM = wid & 3;
    const int warpN = wid >> 2;
    const int rowBase = blockIdx.x * 128;
    const int tile0 = blockIdx.x * 8 + warpM * 2;

    #pragma unroll
    for (int h = 0; h < 2; h++) {
        float acc[2][8][4];
        #pragma unroll
        for (int t = 0; t < 2; t++)
            #pragma unroll
            for (int nt = 0; nt < 8; nt++)
                #pragma unroll
                for (int e = 0; e < 4; e++)
                    acc[t][nt][e] = 0.f;

        const uint2* __restrict__ wf = g_Wfrag
            + (((size_t)h * 16) * 16 + (size_t)warpN * 8) * 32 + lane;

        #pragma unroll 4
        for (int k16 = 0; k16 < 16; k16++) {
            uint4 aH[2];
            #pragma unroll
            for (int t = 0; t < 2; t++)
                aH[t] = __ldg(&g_Xfrag[(size_t)((tile0 + t) * 16 + k16) * 32 + lane]);
            const uint2* bp = wf + (size_t)(k16 * 16) * 32;
            #pragma unroll
            for (int nt = 0; nt < 8; nt++) {
                uint2 b = __ldg(bp + nt * 32);
                mma_f16(acc[0][nt], &aH[0].x, b);
                mma_f16(acc[1][nt], &aH[1].x, b);
            }
        }

        // epilogue: fp16 stores for this half
        #pragma unroll
        for (int t = 0; t < 2; t++) {
            #pragma unroll
            for (int nt = 0; nt < 8; nt++) {
                int row0 = rowBase + warpM * 32 + t * 16 + (lane >> 2);
                int col  = h * 128 + warpN * 64 + nt * 8 + (lane & 3) * 2;
                if (row0 < M)
                    *reinterpret_cast<__half2*>(g_Yh + (size_t)row0 * 256 + col) =
                        __floats2half2_rn(acc[t][nt][0], acc[t][nt][1]);
                int row1 = row0 + 8;
                if (row1 < M)
                    *reinterpret_cast<__half2*>(g_Yh + (size_t)row1 * 256 + col) =
                        __floats2half2_rn(acc[t][nt][2], acc[t][nt][3]);
            }
        }
    }
}

// ---------------------------------------------------------------------------
// CSR build
// ---------------------------------------------------------------------------
__global__ void zero_cnt_kernel(int M) {
    int i = blockIdx.x * blockDim.x + threadIdx.x;
    if (i < M) g_cnt[i] = 0;
}

__global__ void hist_kernel(const int* __restrict__ erow, int E) {
    int i = blockIdx.x * blockDim.x + threadIdx.x;
    if (i < E) atomicAdd(&g_cnt[erow[i]], 1);
}

__global__ __launch_bounds__(SCAN_B)
void scan1_kernel(int M) {
    __shared__ int sh[SCAN_B];
    int tid = threadIdx.x;
    int i = blockIdx.x * SCAN_B + tid;
    int v = (i < M) ? g_cnt[i] : 0;
    sh[tid] = v;
    __syncthreads();
    #pragma unroll
    for (int d = 1; d < SCAN_B; d <<= 1) {
        int t = (tid >= d) ? sh[tid - d] : 0;
        __syncthreads();
        sh[tid] += t;
        __syncthreads();
    }
    if (i < M) g_off[i] = sh[tid] - v;
    if (tid == SCAN_B - 1) g_part[blockIdx.x] = sh[tid];
}

__global__ __launch_bounds__(256)
void scan3_kernel(int M, int E, int nb) {
    __shared__ int sh[MAX_SCAN_BLOCKS];
    int tid = threadIdx.x;
    if (tid < MAX_SCAN_BLOCKS) {
        int v = (tid < nb) ? g_part[tid] : 0;
        sh[tid] = v;
    }
    __syncthreads();
    if (tid < MAX_SCAN_BLOCKS) {
        #pragma unroll
        for (int d = 1; d < MAX_SCAN_BLOCKS; d <<= 1) {
            int t = (tid >= d) ? sh[tid - d] : 0;
            __syncthreads();
            sh[tid] += t;
            __syncthreads();
        }
    } else {
        #pragma unroll
        for (int d = 1; d < MAX_SCAN_BLOCKS; d <<= 1) {
            __syncthreads();
            __syncthreads();
        }
    }
    int i = blockIdx.x * blockDim.x + tid;
    if (i < M) {
        int b = i >> 10;
        int pre = (b == 0) ? 0 : sh[b - 1];
        int o = g_off[i] + pre;
        g_off[i] = o;
        g_cur[i] = o;
    }
    if (i == 0) g_off[M] = E;
}

__global__ void assign_kernel(const int* __restrict__ erow,
                              const int* __restrict__ ecol,
                              const float* __restrict__ eval, int E) {
    int i = blockIdx.x * blockDim.x + threadIdx.x;
    if (i < E) {
        int r = erow[i];
        int p = atomicAdd(&g_cur[r], 1);
        g_cv[p] = make_int2(ecol[i], __float_as_int(eval[i]));
    }
}

// ---------------------------------------------------------------------------
// SpMM over CSR: one warp per row; fp16 Y gather (one LDG.128 = 8 halves per
// lane per edge), fp32 register accumulation, bias fused.
// ---------------------------------------------------------------------------
__device__ __forceinline__ void acc_edge(float* a, uint4 y, float v) {
    float2 f;
    f = __half22float2(*reinterpret_cast<__half2*>(&y.x));
    a[0] += v * f.x; a[1] += v * f.y;
    f = __half22float2(*reinterpret_cast<__half2*>(&y.y));
    a[2] += v * f.x; a[3] += v * f.y;
    f = __half22float2(*reinterpret_cast<__half2*>(&y.z));
    a[4] += v * f.x; a[5] += v * f.y;
    f = __half22float2(*reinterpret_cast<__half2*>(&y.w));
    a[6] += v * f.x; a[7] += v * f.y;
}

__global__ __launch_bounds__(256)
void spmm_csr_kernel(const float* __restrict__ bias,
                     float* __restrict__ out, int M) {
    int warp = (blockIdx.x * blockDim.x + threadIdx.x) >> 5;
    int lane = threadIdx.x & 31;
    if (warp >= M) return;

    int start = g_off[warp];
    int end   = g_off[warp + 1];

    float a[8];
    {
        float4 b0 = reinterpret_cast<const float4*>(bias)[lane * 2 + 0];
        float4 b1 = reinterpret_cast<const float4*>(bias)[lane * 2 + 1];
        a[0] = b0.x; a[1] = b0.y; a[2] = b0.z; a[3] = b0.w;
        a[4] = b1.x; a[5] = b1.y; a[6] = b1.z; a[7] = b1.w;
    }

    for (int base = start; base < end; base += 32) {
        int idx = base + lane;
        int2 cvl = make_int2(0, 0);
        if (idx < end) cvl = g_cv[idx];
        int n = min(32, end - base);

        int j = 0;
        for (; j + 2 <= n; j += 2) {
            int   c0 = __shfl_sync(0xffffffffu, cvl.x, j);
            float v0 = __int_as_float(__shfl_sync(0xffffffffu, cvl.y, j));
            int   c1 = __shfl_sync(0xffffffffu, cvl.x, j + 1);
            float v1 = __int_as_float(__shfl_sync(0xffffffffu, cvl.y, j + 1));
            uint4 y0 = __ldg(reinterpret_cast<const uint4*>(
                g_Yh + (size_t)c0 * DIM) + lane);
            uint4 y1 = __ldg(reinterpret_cast<const uint4*>(
                g_Yh + (size_t)c1 * DIM) + lane);
            acc_edge(a, y0, v0);
            acc_edge(a, y1, v1);
        }
        if (j < n) {
            int   c0 = __shfl_sync(0xffffffffu, cvl.x, j);
            float v0 = __int_as_float(__shfl_sync(0xffffffffu, cvl.y, j));
            uint4 y0 = __ldg(reinterpret_cast<const uint4*>(
                g_Yh + (size_t)c0 * DIM) + lane);
            acc_edge(a, y0, v0);
        }
    }

    float4* o = reinterpret_cast<float4*>(out + (size_t)warp * DIM) + lane * 2;
    o[0] = make_float4(a[0], a[1], a[2], a[3]);
    o[1] = make_float4(a[4], a[5], a[6], a[7]);
}

// ---------------------------------------------------------------------------
// Launch: single side stream for CSR (clean topology).
// ---------------------------------------------------------------------------
extern "C" void kernel_launch(void* const* d_in, const int* in_sizes, int n_in,
                              void* d_out, int out_size) {
    const float* X    = (const float*)d_in[0];
    const int*   erow = (const int*)  d_in[1];
    const int*   ecol = (const int*)  d_in[2];
    const float* eval = (const float*)d_in[3];
    const float* W    = (const float*)d_in[4];
    const float* bias = (const float*)d_in[5];
    float* out = (float*)d_out;

    int M = in_sizes[0] / DIM;   // 100000
    int E = in_sizes[1];         // 1600000
    int nScanBlocks = (M + SCAN_B - 1) / SCAN_B;
    int nTiles = (M + 127) / 128;

    cudaStream_t s2;
    cudaEvent_t ev0, evCsr;
    cudaStreamCreateWithFlags(&s2, cudaStreamNonBlocking);
    cudaEventCreateWithFlags(&ev0, cudaEventDisableTiming);
    cudaEventCreateWithFlags(&evCsr, cudaEventDisableTiming);

    // fork s2 off origin
    cudaEventRecord(ev0, 0);
    cudaStreamWaitEvent(s2, ev0, 0);

    // launch order (ncu profiles launch #4 = gemm):
    wprep_kernel<<<16384 / 256, 256>>>(W);                              // #1
    xprep_kernel<<<(MAX_TILES * 16 * 32) / 256, 256>>>(X, M);           // #2
    zero_cnt_kernel<<<(M + 255) / 256, 256, 0, s2>>>(M);                // #3
    gemm_tc_kernel<<<nTiles, 256>>>(M);                                 // #4
    hist_kernel<<<(E + 255) / 256, 256, 0, s2>>>(erow, E);              // #5
    scan1_kernel<<<nScanBlocks, SCAN_B, 0, s2>>>(M);                    // #6
    scan3_kernel<<<(M + 255) / 256, 256, 0, s2>>>(M, E, nScanBlocks);   // #7
    assign_kernel<<<(E + 255) / 256, 256, 0, s2>>>(erow, ecol, eval, E);// #8

    // join
    cudaEventRecord(evCsr, s2);
    cudaStreamWaitEvent(0, evCsr, 0);

    // out[r] = bias + sum_e v * Y[c]
    int rows_per_block = 256 / 32;
    spmm_csr_kernel<<<(M + rows_per_block - 1) / rows_per_block, 256>>>(bias, out, M); // #9
}